// round 2
// baseline (speedup 1.0000x reference)
#include <cuda_runtime.h>
#include <cstdint>

// ---------------------------------------------------------------------------
// AttentionRAR: x -> qkv GEMM -> causal flash attention -> proj GEMM (+bias)
// B=4, N=2048, C=1024, H=16, D=64
// Baseline: fp32 SIMT, register-tiled GEMMs + flash attention.
// ---------------------------------------------------------------------------

#define BATCH 4
#define SEQ   2048
#define CH    1024
#define HEADS 16
#define HDIM  64
#define ROWS  (BATCH * SEQ)       // 8192
#define QKV_C (3 * CH)            // 3072

// Scratch (static device globals — allowed; no runtime allocation)
__device__ float g_qkv[(size_t)ROWS * QKV_C];   // [8192][3072]
__device__ float g_attn[(size_t)ROWS * CH];     // [8192][1024]

// ---------------------------------------------------------------------------
// SGEMM: C[M,N] = A[M,K] * B[K,N] (+ bias[N]); all row-major.
// 128x128 block tile, BK=16, 256 threads, 8x8 per-thread micro-tile.
// ---------------------------------------------------------------------------
template<bool BIAS>
__global__ __launch_bounds__(256, 2)
void sgemm128(const float* __restrict__ A, const float* __restrict__ B,
              const float* __restrict__ bias, float* __restrict__ C,
              int M, int N, int K)
{
    __shared__ float As[16][132];   // [k][m], padded
    __shared__ float Bs[16][128];   // [k][n]

    const int tid = threadIdx.x;
    const int tx = tid & 15;        // 0..15 -> N direction
    const int ty = tid >> 4;        // 0..15 -> M direction
    const int m0 = blockIdx.y * 128;
    const int n0 = blockIdx.x * 128;

    const int arow = tid >> 2;          // 0..63
    const int acol = (tid & 3) << 2;    // 0,4,8,12
    const int brow = tid >> 5;          // 0..7
    const int bcol = (tid & 31) << 2;   // 0..124

    float acc[8][8];
    #pragma unroll
    for (int i = 0; i < 8; i++)
        #pragma unroll
        for (int j = 0; j < 8; j++) acc[i][j] = 0.0f;

    for (int k0 = 0; k0 < K; k0 += 16) {
        // prefetch global tiles into registers
        float4 a0 = *(const float4*)&A[(size_t)(m0 + arow)      * K + k0 + acol];
        float4 a1 = *(const float4*)&A[(size_t)(m0 + arow + 64) * K + k0 + acol];
        float4 b0 = *(const float4*)&B[(size_t)(k0 + brow)     * N + n0 + bcol];
        float4 b1 = *(const float4*)&B[(size_t)(k0 + brow + 8) * N + n0 + bcol];

        __syncthreads();   // previous iteration's compute done before overwrite

        As[acol + 0][arow] = a0.x;  As[acol + 1][arow] = a0.y;
        As[acol + 2][arow] = a0.z;  As[acol + 3][arow] = a0.w;
        As[acol + 0][arow + 64] = a1.x;  As[acol + 1][arow + 64] = a1.y;
        As[acol + 2][arow + 64] = a1.z;  As[acol + 3][arow + 64] = a1.w;
        *(float4*)&Bs[brow][bcol]     = b0;
        *(float4*)&Bs[brow + 8][bcol] = b1;

        __syncthreads();

        #pragma unroll
        for (int k = 0; k < 16; k++) {
            float4 x0 = *(const float4*)&As[k][ty * 8];
            float4 x1 = *(const float4*)&As[k][ty * 8 + 4];
            float4 y0 = *(const float4*)&Bs[k][tx * 8];
            float4 y1 = *(const float4*)&Bs[k][tx * 8 + 4];
            float a8[8] = {x0.x, x0.y, x0.z, x0.w, x1.x, x1.y, x1.z, x1.w};
            float b8[8] = {y0.x, y0.y, y0.z, y0.w, y1.x, y1.y, y1.z, y1.w};
            #pragma unroll
            for (int i = 0; i < 8; i++)
                #pragma unroll
                for (int j = 0; j < 8; j++)
                    acc[i][j] += a8[i] * b8[j];
        }
    }

    float bb[8];
    #pragma unroll
    for (int j = 0; j < 8; j++)
        bb[j] = BIAS ? bias[n0 + tx * 8 + j] : 0.0f;

    #pragma unroll
    for (int i = 0; i < 8; i++) {
        float4 c0, c1;
        c0.x = acc[i][0] + bb[0];  c0.y = acc[i][1] + bb[1];
        c0.z = acc[i][2] + bb[2];  c0.w = acc[i][3] + bb[3];
        c1.x = acc[i][4] + bb[4];  c1.y = acc[i][5] + bb[5];
        c1.z = acc[i][6] + bb[6];  c1.w = acc[i][7] + bb[7];
        float* cp = &C[(size_t)(m0 + ty * 8 + i) * N + n0 + tx * 8];
        *(float4*)cp       = c0;
        *(float4*)(cp + 4) = c1;
    }
}

// ---------------------------------------------------------------------------
// Causal flash attention.
// Grid: (SEQ/128, B*H). Block: 256 threads (tx 0..15 over keys/headdim,
// ty 0..15 over 8-row groups). Each block: 128 query rows of one (b,h).
// KV streamed in 64-key tiles; online softmax; causal tiles skipped.
// qkv layout per row n of batch b: [3][H][D] at ((b*SEQ+n)*3072).
// ---------------------------------------------------------------------------
#define AT_SMEM_FLOATS (64*132 + 64*68 + 64*68 + 128*68)
#define AT_SMEM_BYTES  (AT_SMEM_FLOATS * 4)

__global__ __launch_bounds__(256, 2)
void flash_attn(const float* __restrict__ qkv, float* __restrict__ outb)
{
    extern __shared__ float sm[];
    float* QT = sm;                 // [d][r]  64 x 132
    float* KT = QT + 64 * 132;      // [d][c]  64 x 68
    float* Vs = KT + 64 * 68;       // [c][d]  64 x 68
    float* PS = Vs + 64 * 68;       // [r][c] 128 x 68

    const int tid = threadIdx.x;
    const int tx = tid & 15;
    const int ty = tid >> 4;
    const int bh = blockIdx.y;
    const int b  = bh >> 4;
    const int h  = bh & 15;
    const int m0 = blockIdx.x * 128;

    const float* Qg = qkv + (size_t)b * SEQ * QKV_C + h * HDIM;
    const float* Kg = Qg + CH;
    const float* Vg = Qg + 2 * CH;

    // Load + transpose Q tile: QT[d][r]
    for (int i = tid; i < 128 * 16; i += 256) {      // float4 granules
        int r  = i >> 4;
        int d4 = (i & 15) << 2;
        float4 q = *(const float4*)&Qg[(size_t)(m0 + r) * QKV_C + d4];
        QT[(d4 + 0) * 132 + r] = q.x;
        QT[(d4 + 1) * 132 + r] = q.y;
        QT[(d4 + 2) * 132 + r] = q.z;
        QT[(d4 + 3) * 132 + r] = q.w;
    }

    float m_i[8], l_i[8], O[8][4];
    #pragma unroll
    for (int rr = 0; rr < 8; rr++) {
        m_i[rr] = -1e30f;  l_i[rr] = 0.0f;
        O[rr][0] = O[rr][1] = O[rr][2] = O[rr][3] = 0.0f;
    }

    const int ntiles = (m0 >> 6) + 2;   // keys up to m0+127 (causal)
    for (int t = 0; t < ntiles; t++) {
        const int k0 = t << 6;

        __syncthreads();    // prior PV phase done before overwriting KT/Vs
        for (int i = tid; i < 64 * 16; i += 256) {
            int c  = i >> 4;
            int d4 = (i & 15) << 2;
            size_t g = (size_t)(k0 + c) * QKV_C + d4;
            float4 kk = *(const float4*)&Kg[g];
            float4 vv = *(const float4*)&Vg[g];
            KT[(d4 + 0) * 68 + c] = kk.x;
            KT[(d4 + 1) * 68 + c] = kk.y;
            KT[(d4 + 2) * 68 + c] = kk.z;
            KT[(d4 + 3) * 68 + c] = kk.w;
            *(float4*)&Vs[c * 68 + d4] = vv;
        }
        __syncthreads();

        // S = Q K^T  (outer product over d)
        float s[8][4];
        #pragma unroll
        for (int rr = 0; rr < 8; rr++)
            s[rr][0] = s[rr][1] = s[rr][2] = s[rr][3] = 0.0f;

        #pragma unroll 8
        for (int d = 0; d < 64; d++) {
            float4 x0 = *(const float4*)&QT[d * 132 + ty * 8];
            float4 x1 = *(const float4*)&QT[d * 132 + ty * 8 + 4];
            float4 kk = *(const float4*)&KT[d * 68 + tx * 4];
            float a8[8] = {x0.x, x0.y, x0.z, x0.w, x1.x, x1.y, x1.z, x1.w};
            float b4[4] = {kk.x, kk.y, kk.z, kk.w};
            #pragma unroll
            for (int rr = 0; rr < 8; rr++)
                #pragma unroll
                for (int cc = 0; cc < 4; cc++)
                    s[rr][cc] += a8[rr] * b4[cc];
        }

        const bool need_mask = (k0 + 63 > m0);

        // online softmax update per row
        #pragma unroll
        for (int rr = 0; rr < 8; rr++) {
            const int qi = m0 + ty * 8 + rr;
            float tmax = -1e30f;
            #pragma unroll
            for (int cc = 0; cc < 4; cc++) {
                float v = s[rr][cc] * 0.125f;   // 1/sqrt(64)
                if (need_mask && (k0 + tx * 4 + cc > qi)) v = -1e30f;
                s[rr][cc] = v;
                tmax = fmaxf(tmax, v);
            }
            #pragma unroll
            for (int o = 8; o; o >>= 1)
                tmax = fmaxf(tmax, __shfl_xor_sync(0xffffffffu, tmax, o, 16));

            float mnew = fmaxf(m_i[rr], tmax);
            float corr = __expf(m_i[rr] - mnew);
            m_i[rr] = mnew;

            float rsum = 0.0f;
            #pragma unroll
            for (int cc = 0; cc < 4; cc++) {
                float p = __expf(s[rr][cc] - mnew);
                s[rr][cc] = p;
                rsum += p;
            }
            #pragma unroll
            for (int o = 8; o; o >>= 1)
                rsum += __shfl_xor_sync(0xffffffffu, rsum, o, 16);

            l_i[rr] = l_i[rr] * corr + rsum;
            O[rr][0] *= corr;  O[rr][1] *= corr;
            O[rr][2] *= corr;  O[rr][3] *= corr;

            *(float4*)&PS[(ty * 8 + rr) * 68 + tx * 4] =
                make_float4(s[rr][0], s[rr][1], s[rr][2], s[rr][3]);
        }
        __syncthreads();

        // O += P @ V
        #pragma unroll 4
        for (int c = 0; c < 64; c += 4) {
            float4 v0 = *(const float4*)&Vs[(c + 0) * 68 + tx * 4];
            float4 v1 = *(const float4*)&Vs[(c + 1) * 68 + tx * 4];
            float4 v2 = *(const float4*)&Vs[(c + 2) * 68 + tx * 4];
            float4 v3 = *(const float4*)&Vs[(c + 3) * 68 + tx * 4];
            #pragma unroll
            for (int rr = 0; rr < 8; rr++) {
                float4 p4 = *(const float4*)&PS[(ty * 8 + rr) * 68 + c];
                O[rr][0] += p4.x * v0.x + p4.y * v1.x + p4.z * v2.x + p4.w * v3.x;
                O[rr][1] += p4.x * v0.y + p4.y * v1.y + p4.z * v2.y + p4.w * v3.y;
                O[rr][2] += p4.x * v0.z + p4.y * v1.z + p4.z * v2.z + p4.w * v3.z;
                O[rr][3] += p4.x * v0.w + p4.y * v1.w + p4.z * v2.w + p4.w * v3.w;
            }
        }
    }

    // normalize + write: attn[b][n][h*64 + d]
    float* Og = outb + (size_t)b * SEQ * CH + h * HDIM;
    #pragma unroll
    for (int rr = 0; rr < 8; rr++) {
        float inv = 1.0f / l_i[rr];
        float4 o4 = make_float4(O[rr][0] * inv, O[rr][1] * inv,
                                O[rr][2] * inv, O[rr][3] * inv);
        *(float4*)&Og[(size_t)(m0 + ty * 8 + rr) * CH + tx * 4] = o4;
    }
}

// ---------------------------------------------------------------------------
extern "C" void kernel_launch(void* const* d_in, const int* in_sizes, int n_in,
                              void* d_out, int out_size)
{
    const float* x     = (const float*)d_in[0];
    // d_in[1] = attn_mask (exact causal -1e9 mask) — implemented directly
    const float* Wqkv  = (const float*)d_in[2];
    const float* Wproj = (const float*)d_in[3];
    const float* bproj = (const float*)d_in[4];
    float* out = (float*)d_out;

    void* p_qkv = nullptr;
    void* p_attn = nullptr;
    cudaGetSymbolAddress(&p_qkv, g_qkv);
    cudaGetSymbolAddress(&p_attn, g_attn);
    float* qkv  = (float*)p_qkv;
    float* attn = (float*)p_attn;

    cudaFuncSetAttribute(flash_attn,
                         cudaFuncAttributeMaxDynamicSharedMemorySize,
                         AT_SMEM_BYTES);

    // 1) qkv = x @ W_qkv            [8192,1024] x [1024,3072]
    dim3 g1(QKV_C / 128, ROWS / 128);
    sgemm128<false><<<g1, 256>>>(x, Wqkv, nullptr, qkv, ROWS, QKV_C, CH);

    // 2) causal flash attention -> attn [8192,1024]
    dim3 g2(SEQ / 128, BATCH * HEADS);
    flash_attn<<<g2, 256, AT_SMEM_BYTES>>>(qkv, attn);

    // 3) out = attn @ W_proj + b    [8192,1024] x [1024,1024]
    dim3 g3(CH / 128, ROWS / 128);
    sgemm128<true><<<g3, 256>>>(attn, Wproj, bproj, out, ROWS, CH, CH);
}

// round 7
// speedup vs baseline: 1.4272x; 1.4272x over previous
#include <cuda_runtime.h>
#include <cuda_bf16.h>
#include <cstdint>

// ---------------------------------------------------------------------------
// AttentionRAR: x -> qkv GEMM -> causal flash attention -> proj GEMM (+bias)
// B=4, N=2048, C=1024, H=16, D=64
// GEMMs: mma.sync bf16 (legacy tensor path, sm_103-safe) with 3-term
// precision split folded into K (1024 -> 3072).
// Attention: fp32 SIMT flash (proven in R2).
// ---------------------------------------------------------------------------

#define BATCH 4
#define SEQ   2048
#define CH    1024
#define HEADS 16
#define HDIM  64
#define ROWS  (BATCH * SEQ)       // 8192
#define QKV_C (3 * CH)            // 3072
#define K3    (3 * CH)            // split K = 3072

// Scratch (static device globals)
__device__ __align__(1024) float g_qkv[(size_t)ROWS * QKV_C];
__device__ __align__(1024) float g_attn[(size_t)ROWS * CH];
__device__ __align__(1024) __nv_bfloat16 g_xs[(size_t)ROWS * K3];
__device__ __align__(1024) __nv_bfloat16 g_as[(size_t)ROWS * K3];
__device__ __align__(1024) __nv_bfloat16 g_wqkt[(size_t)QKV_C * K3];
__device__ __align__(1024) __nv_bfloat16 g_wpt[(size_t)CH * K3];

// ======================= helpers ===========================================
__device__ __forceinline__ uint32_t smem_u32(const void* p) {
    uint32_t a;
    asm("{ .reg .u64 t; cvta.to.shared.u64 t, %1; cvt.u32.u64 %0, t; }"
        : "=r"(a) : "l"(p));
    return a;
}

#define CP_ASYNC16(sm, gp) \
    asm volatile("cp.async.cg.shared.global [%0], [%1], 16;" :: "r"(sm), "l"(gp))
#define CP_COMMIT() asm volatile("cp.async.commit_group;" ::: "memory")
#define CP_WAIT1()  asm volatile("cp.async.wait_group 1;" ::: "memory")
#define CP_WAIT0()  asm volatile("cp.async.wait_group 0;" ::: "memory")

__device__ __forceinline__ void ldsm_x4(uint32_t& r0, uint32_t& r1,
                                        uint32_t& r2, uint32_t& r3, uint32_t a) {
    asm volatile("ldmatrix.sync.aligned.m8n8.x4.shared.b16 {%0,%1,%2,%3}, [%4];"
                 : "=r"(r0), "=r"(r1), "=r"(r2), "=r"(r3) : "r"(a));
}

__device__ __forceinline__ void mma16816(float* c, const uint32_t* a,
                                         const uint32_t* b) {
    asm volatile("mma.sync.aligned.m16n8k16.row.col.f32.bf16.bf16.f32 "
                 "{%0,%1,%2,%3}, {%4,%5,%6,%7}, {%8,%9}, {%0,%1,%2,%3};"
                 : "+f"(c[0]), "+f"(c[1]), "+f"(c[2]), "+f"(c[3])
                 : "r"(a[0]), "r"(a[1]), "r"(a[2]), "r"(a[3]),
                   "r"(b[0]), "r"(b[1]));
}

// ---------------------------------------------------------------------------
// Split conversions: a = hi + lo (bf16). A rows: [hi, hi, lo]; W^T: [hi, lo, hi]
// ---------------------------------------------------------------------------
__global__ void split_rows(const float* __restrict__ in, __nv_bfloat16* __restrict__ out)
{
    size_t i = (size_t)blockIdx.x * blockDim.x + threadIdx.x;   // over ROWS*CH
    int r = (int)(i >> 10);
    int k = (int)(i & 1023);
    float a = in[i];
    __nv_bfloat16 hi = __float2bfloat16(a);
    __nv_bfloat16 lo = __float2bfloat16(a - __bfloat162float(hi));
    __nv_bfloat16* o = out + (size_t)r * K3;
    o[k] = hi; o[CH + k] = hi; o[2 * CH + k] = lo;
}

// W [K=CH, N] fp32 -> Wt [N, 3K] bf16: [0,K)=hi, [K,2K)=lo, [2K,3K)=hi
__global__ void split_wT(const float* __restrict__ W, __nv_bfloat16* __restrict__ Wt, int N)
{
    __shared__ float t[32][33];
    int n0 = blockIdx.x * 32, k0 = blockIdx.y * 32;
    int tx = threadIdx.x, ty = threadIdx.y;   // 32 x 8
    #pragma unroll
    for (int j = 0; j < 32; j += 8)
        t[ty + j][tx] = W[(size_t)(k0 + ty + j) * N + n0 + tx];
    __syncthreads();
    #pragma unroll
    for (int j = 0; j < 32; j += 8) {
        float a = t[tx][ty + j];
        __nv_bfloat16 hi = __float2bfloat16(a);
        __nv_bfloat16 lo = __float2bfloat16(a - __bfloat162float(hi));
        __nv_bfloat16* o = Wt + (size_t)(n0 + ty + j) * K3 + k0 + tx;
        o[0] = hi; o[CH] = lo; o[2 * CH] = hi;
    }
}

// ---------------------------------------------------------------------------
// mma.sync bf16 GEMM: C[M,N] = A[M,K3] * Bt[N,K3]^T (+bias), fp32 out.
// 128x128 CTA tile, BK=32, 8 warps (2x4), warp tile 64x32, double-buffered.
// ---------------------------------------------------------------------------
#define BK   32
#define LDSW 40            // smem row stride in elems (32 + 8 pad)
#define NCHUNK (K3 / BK)   // 96

template<bool BIAS>
__global__ __launch_bounds__(256)
void gemm_mma(const __nv_bfloat16* __restrict__ A, const __nv_bfloat16* __restrict__ Bt,
              const float* __restrict__ bias, float* __restrict__ C, int N)
{
    __shared__ __nv_bfloat16 As[2][128 * LDSW];
    __shared__ __nv_bfloat16 Bs[2][128 * LDSW];

    const int tid  = threadIdx.x;
    const int lane = tid & 31;
    const int warp = tid >> 5;
    const int wm   = warp >> 2;      // 0..1 : M
    const int wn   = warp & 3;       // 0..3 : N
    const int m0   = blockIdx.y * 128;
    const int n0   = blockIdx.x * 128;

    uint32_t sA[2] = { smem_u32(As[0]), smem_u32(As[1]) };
    uint32_t sB[2] = { smem_u32(Bs[0]), smem_u32(Bs[1]) };

    // cp.async mapping: 512 16B chunks per tile; thread handles chunks tid, tid+256
    const int crow = tid >> 2;             // 0..63
    const int ckp  = (tid & 3) * 8;        // k offset in elems (0,8,16,24)
    const uint32_t so0 = (uint32_t)(crow * LDSW + ckp) * 2;
    const uint32_t so1 = (uint32_t)((crow + 64) * LDSW + ckp) * 2;

    auto load = [&](int kc, int buf) {
        const __nv_bfloat16* Ag = A + (size_t)(m0 + crow) * K3 + kc * BK + ckp;
        const __nv_bfloat16* Bg = Bt + (size_t)(n0 + crow) * K3 + kc * BK + ckp;
        CP_ASYNC16(sA[buf] + so0, Ag);
        CP_ASYNC16(sA[buf] + so1, Ag + (size_t)64 * K3);
        CP_ASYNC16(sB[buf] + so0, Bg);
        CP_ASYNC16(sB[buf] + so1, Bg + (size_t)64 * K3);
    };

    // ldmatrix per-thread address components
    const int lmat = lane >> 3;            // matrix index 0..3
    const int lrow = lane & 7;
    // A: mat bit0 -> +8 rows, mat bit1 -> +8 k
    const int a_row_base = wm * 64 + ((lmat & 1) << 3) + lrow;
    const int a_k_off    = (lmat >> 1) << 3;
    // B: mat bit1 -> +8 n (next n8 frag), mat bit0 -> +8 k
    const int b_row_base = wn * 32 + ((lmat >> 1) << 3) + lrow;
    const int b_k_off    = (lmat & 1) << 3;

    float acc[4][4][4];
    #pragma unroll
    for (int i = 0; i < 4; i++)
        #pragma unroll
        for (int j = 0; j < 4; j++)
            #pragma unroll
            for (int q = 0; q < 4; q++) acc[i][j][q] = 0.0f;

    load(0, 0);
    CP_COMMIT();

    for (int t = 0; t < NCHUNK; t++) {
        const int buf = t & 1;
        if (t + 1 < NCHUNK) {
            load(t + 1, buf ^ 1);
            CP_COMMIT();
            CP_WAIT1();
        } else {
            CP_WAIT0();
        }
        __syncthreads();

        #pragma unroll
        for (int ks = 0; ks < 2; ks++) {
            uint32_t a[4][4];
            #pragma unroll
            for (int mt = 0; mt < 4; mt++) {
                uint32_t ad = sA[buf] +
                    (uint32_t)((a_row_base + mt * 16) * LDSW + ks * 16 + a_k_off) * 2;
                ldsm_x4(a[mt][0], a[mt][1], a[mt][2], a[mt][3], ad);
            }
            uint32_t b[2][4];
            #pragma unroll
            for (int jj = 0; jj < 2; jj++) {
                uint32_t bd = sB[buf] +
                    (uint32_t)((b_row_base + jj * 16) * LDSW + ks * 16 + b_k_off) * 2;
                ldsm_x4(b[jj][0], b[jj][1], b[jj][2], b[jj][3], bd);
            }
            #pragma unroll
            for (int mt = 0; mt < 4; mt++)
                #pragma unroll
                for (int nf = 0; nf < 4; nf++)
                    mma16816(acc[mt][nf], a[mt], &b[nf >> 1][(nf & 1) * 2]);
        }
        __syncthreads();
    }

    // epilogue: acc frag (mt, nf): rows m0+wm*64+mt*16+lane/4 (+8), cols n0+wn*32+nf*8+(lane%4)*2
    const int em = m0 + wm * 64 + (lane >> 2);
    const int en = n0 + wn * 32 + (lane & 3) * 2;
    #pragma unroll
    for (int mt = 0; mt < 4; mt++) {
        #pragma unroll
        for (int nf = 0; nf < 4; nf++) {
            float b0 = 0.f, b1 = 0.f;
            if (BIAS) { b0 = bias[en + nf * 8]; b1 = bias[en + nf * 8 + 1]; }
            float* c0 = C + (size_t)(em + mt * 16) * N + en + nf * 8;
            float* c1 = C + (size_t)(em + mt * 16 + 8) * N + en + nf * 8;
            float2 v0 = make_float2(acc[mt][nf][0] + b0, acc[mt][nf][1] + b1);
            float2 v1 = make_float2(acc[mt][nf][2] + b0, acc[mt][nf][3] + b1);
            *(float2*)c0 = v0;
            *(float2*)c1 = v1;
        }
    }
}

// ---------------------------------------------------------------------------
// Causal flash attention (fp32 SIMT, unchanged from R2 passing version)
// ---------------------------------------------------------------------------
#define AT_SMEM_FLOATS (64*132 + 64*68 + 64*68 + 128*68)
#define AT_SMEM_BYTES  (AT_SMEM_FLOATS * 4)

__global__ __launch_bounds__(256, 2)
void flash_attn(const float* __restrict__ qkv, float* __restrict__ outb)
{
    extern __shared__ float sm[];
    float* QT = sm;                 // [d][r]  64 x 132
    float* KT = QT + 64 * 132;      // [d][c]  64 x 68
    float* Vs = KT + 64 * 68;       // [c][d]  64 x 68
    float* PS = Vs + 64 * 68;       // [r][c] 128 x 68

    const int tid = threadIdx.x;
    const int tx = tid & 15;
    const int ty = tid >> 4;
    const int bh = blockIdx.y;
    const int b  = bh >> 4;
    const int h  = bh & 15;
    const int m0 = blockIdx.x * 128;

    const float* Qg = qkv + (size_t)b * SEQ * QKV_C + h * HDIM;
    const float* Kg = Qg + CH;
    const float* Vg = Qg + 2 * CH;

    for (int i = tid; i < 128 * 16; i += 256) {
        int r  = i >> 4;
        int d4 = (i & 15) << 2;
        float4 q = *(const float4*)&Qg[(size_t)(m0 + r) * QKV_C + d4];
        QT[(d4 + 0) * 132 + r] = q.x;
        QT[(d4 + 1) * 132 + r] = q.y;
        QT[(d4 + 2) * 132 + r] = q.z;
        QT[(d4 + 3) * 132 + r] = q.w;
    }

    float m_i[8], l_i[8], O[8][4];
    #pragma unroll
    for (int rr = 0; rr < 8; rr++) {
        m_i[rr] = -1e30f;  l_i[rr] = 0.0f;
        O[rr][0] = O[rr][1] = O[rr][2] = O[rr][3] = 0.0f;
    }

    const int ntiles = (m0 >> 6) + 2;
    for (int t = 0; t < ntiles; t++) {
        const int k0 = t << 6;

        __syncthreads();
        for (int i = tid; i < 64 * 16; i += 256) {
            int c  = i >> 4;
            int d4 = (i & 15) << 2;
            size_t g = (size_t)(k0 + c) * QKV_C + d4;
            float4 kk = *(const float4*)&Kg[g];
            float4 vv = *(const float4*)&Vg[g];
            KT[(d4 + 0) * 68 + c] = kk.x;
            KT[(d4 + 1) * 68 + c] = kk.y;
            KT[(d4 + 2) * 68 + c] = kk.z;
            KT[(d4 + 3) * 68 + c] = kk.w;
            *(float4*)&Vs[c * 68 + d4] = vv;
        }
        __syncthreads();

        float s[8][4];
        #pragma unroll
        for (int rr = 0; rr < 8; rr++)
            s[rr][0] = s[rr][1] = s[rr][2] = s[rr][3] = 0.0f;

        #pragma unroll 8
        for (int d = 0; d < 64; d++) {
            float4 x0 = *(const float4*)&QT[d * 132 + ty * 8];
            float4 x1 = *(const float4*)&QT[d * 132 + ty * 8 + 4];
            float4 kk = *(const float4*)&KT[d * 68 + tx * 4];
            float a8[8] = {x0.x, x0.y, x0.z, x0.w, x1.x, x1.y, x1.z, x1.w};
            float b4[4] = {kk.x, kk.y, kk.z, kk.w};
            #pragma unroll
            for (int rr = 0; rr < 8; rr++)
                #pragma unroll
                for (int cc = 0; cc < 4; cc++)
                    s[rr][cc] += a8[rr] * b4[cc];
        }

        const bool need_mask = (k0 + 63 > m0);

        #pragma unroll
        for (int rr = 0; rr < 8; rr++) {
            const int qi = m0 + ty * 8 + rr;
            float tmax = -1e30f;
            #pragma unroll
            for (int cc = 0; cc < 4; cc++) {
                float v = s[rr][cc] * 0.125f;
                if (need_mask && (k0 + tx * 4 + cc > qi)) v = -1e30f;
                s[rr][cc] = v;
                tmax = fmaxf(tmax, v);
            }
            #pragma unroll
            for (int o = 8; o; o >>= 1)
                tmax = fmaxf(tmax, __shfl_xor_sync(0xffffffffu, tmax, o, 16));

            float mnew = fmaxf(m_i[rr], tmax);
            float corr = __expf(m_i[rr] - mnew);
            m_i[rr] = mnew;

            float rsum = 0.0f;
            #pragma unroll
            for (int cc = 0; cc < 4; cc++) {
                float p = __expf(s[rr][cc] - mnew);
                s[rr][cc] = p;
                rsum += p;
            }
            #pragma unroll
            for (int o = 8; o; o >>= 1)
                rsum += __shfl_xor_sync(0xffffffffu, rsum, o, 16);

            l_i[rr] = l_i[rr] * corr + rsum;
            O[rr][0] *= corr;  O[rr][1] *= corr;
            O[rr][2] *= corr;  O[rr][3] *= corr;

            *(float4*)&PS[(ty * 8 + rr) * 68 + tx * 4] =
                make_float4(s[rr][0], s[rr][1], s[rr][2], s[rr][3]);
        }
        __syncthreads();

        #pragma unroll 4
        for (int c = 0; c < 64; c += 4) {
            float4 v0 = *(const float4*)&Vs[(c + 0) * 68 + tx * 4];
            float4 v1 = *(const float4*)&Vs[(c + 1) * 68 + tx * 4];
            float4 v2 = *(const float4*)&Vs[(c + 2) * 68 + tx * 4];
            float4 v3 = *(const float4*)&Vs[(c + 3) * 68 + tx * 4];
            #pragma unroll
            for (int rr = 0; rr < 8; rr++) {
                float4 p4 = *(const float4*)&PS[(ty * 8 + rr) * 68 + c];
                O[rr][0] += p4.x * v0.x + p4.y * v1.x + p4.z * v2.x + p4.w * v3.x;
                O[rr][1] += p4.x * v0.y + p4.y * v1.y + p4.z * v2.y + p4.w * v3.y;
                O[rr][2] += p4.x * v0.z + p4.y * v1.z + p4.z * v2.z + p4.w * v3.z;
                O[rr][3] += p4.x * v0.w + p4.y * v1.w + p4.z * v2.w + p4.w * v3.w;
            }
        }
    }

    float* Og = outb + (size_t)b * SEQ * CH + h * HDIM;
    #pragma unroll
    for (int rr = 0; rr < 8; rr++) {
        float inv = 1.0f / l_i[rr];
        float4 o4 = make_float4(O[rr][0] * inv, O[rr][1] * inv,
                                O[rr][2] * inv, O[rr][3] * inv);
        *(float4*)&Og[(size_t)(m0 + ty * 8 + rr) * CH + tx * 4] = o4;
    }
}

// ---------------------------------------------------------------------------
extern "C" void kernel_launch(void* const* d_in, const int* in_sizes, int n_in,
                              void* d_out, int out_size)
{
    const float* x     = (const float*)d_in[0];
    const float* Wqkv  = (const float*)d_in[2];
    const float* Wproj = (const float*)d_in[3];
    const float* bproj = (const float*)d_in[4];
    float* out = (float*)d_out;

    void *p_qkv, *p_attn, *p_xs, *p_as, *p_wqkt, *p_wpt;
    cudaGetSymbolAddress(&p_qkv, g_qkv);
    cudaGetSymbolAddress(&p_attn, g_attn);
    cudaGetSymbolAddress(&p_xs, g_xs);
    cudaGetSymbolAddress(&p_as, g_as);
    cudaGetSymbolAddress(&p_wqkt, g_wqkt);
    cudaGetSymbolAddress(&p_wpt, g_wpt);
    float* qkv  = (float*)p_qkv;
    float* attn = (float*)p_attn;
    __nv_bfloat16* xs   = (__nv_bfloat16*)p_xs;
    __nv_bfloat16* as   = (__nv_bfloat16*)p_as;
    __nv_bfloat16* wqkt = (__nv_bfloat16*)p_wqkt;
    __nv_bfloat16* wpt  = (__nv_bfloat16*)p_wpt;

    cudaFuncSetAttribute(flash_attn, cudaFuncAttributeMaxDynamicSharedMemorySize,
                         AT_SMEM_BYTES);

    // conversions
    split_rows<<<(ROWS * CH) / 256, 256>>>(x, xs);
    dim3 wt1(QKV_C / 32, CH / 32);
    split_wT<<<wt1, dim3(32, 8)>>>(Wqkv, wqkt, QKV_C);
    dim3 wt2(CH / 32, CH / 32);
    split_wT<<<wt2, dim3(32, 8)>>>(Wproj, wpt, CH);

    // 1) qkv = x @ W_qkv  (mma.sync bf16, split K)
    dim3 g1(QKV_C / 128, ROWS / 128);
    gemm_mma<false><<<g1, 256>>>(xs, wqkt, nullptr, qkv, QKV_C);

    // 2) causal flash attention
    dim3 g2(SEQ / 128, BATCH * HEADS);
    flash_attn<<<g2, 256, AT_SMEM_BYTES>>>(qkv, attn);

    // 3) convert attn, then out = attn @ W_proj + b
    split_rows<<<(ROWS * CH) / 256, 256>>>(attn, as);
    dim3 g3(CH / 128, ROWS / 128);
    gemm_mma<true><<<g3, 256>>>(as, wpt, bproj, out, CH);
}

// round 8
// speedup vs baseline: 1.7462x; 1.2235x over previous
#include <cuda_runtime.h>
#include <cuda_bf16.h>
#include <cstdint>

// ---------------------------------------------------------------------------
// AttentionRAR: x -> qkv GEMM -> causal flash attention -> proj GEMM (+bias)
// B=4, N=2048, C=1024, H=16, D=64
// All three matmul stages on mma.sync bf16 with 3-term precision split.
// ---------------------------------------------------------------------------

#define BATCH 4
#define SEQ   2048
#define CH    1024
#define HEADS 16
#define HDIM  64
#define ROWS  (BATCH * SEQ)       // 8192
#define QKV_C (3 * CH)            // 3072
#define K3    (3 * CH)            // split K = 3072

// Scratch (static device globals)
__device__ __align__(1024) float g_qkv[(size_t)ROWS * QKV_C];
__device__ __align__(1024) __nv_bfloat16 g_xs[(size_t)ROWS * K3];
__device__ __align__(1024) __nv_bfloat16 g_as[(size_t)ROWS * K3];
__device__ __align__(1024) __nv_bfloat16 g_wqkt[(size_t)QKV_C * K3];
__device__ __align__(1024) __nv_bfloat16 g_wpt[(size_t)CH * K3];

// ======================= helpers ===========================================
__device__ __forceinline__ uint32_t smem_u32(const void* p) {
    uint32_t a;
    asm("{ .reg .u64 t; cvta.to.shared.u64 t, %1; cvt.u32.u64 %0, t; }"
        : "=r"(a) : "l"(p));
    return a;
}

#define CP_ASYNC16(sm, gp) \
    asm volatile("cp.async.cg.shared.global [%0], [%1], 16;" :: "r"(sm), "l"(gp))
#define CP_COMMIT() asm volatile("cp.async.commit_group;" ::: "memory")
#define CP_WAIT2()  asm volatile("cp.async.wait_group 2;" ::: "memory")

__device__ __forceinline__ void ldsm_x4(uint32_t& r0, uint32_t& r1,
                                        uint32_t& r2, uint32_t& r3, uint32_t a) {
    asm volatile("ldmatrix.sync.aligned.m8n8.x4.shared.b16 {%0,%1,%2,%3}, [%4];"
                 : "=r"(r0), "=r"(r1), "=r"(r2), "=r"(r3) : "r"(a));
}
__device__ __forceinline__ void ldsm_x4t(uint32_t& r0, uint32_t& r1,
                                         uint32_t& r2, uint32_t& r3, uint32_t a) {
    asm volatile("ldmatrix.sync.aligned.m8n8.x4.trans.shared.b16 {%0,%1,%2,%3}, [%4];"
                 : "=r"(r0), "=r"(r1), "=r"(r2), "=r"(r3) : "r"(a));
}

__device__ __forceinline__ void mma16816(float* c, const uint32_t* a,
                                         const uint32_t* b) {
    asm volatile("mma.sync.aligned.m16n8k16.row.col.f32.bf16.bf16.f32 "
                 "{%0,%1,%2,%3}, {%4,%5,%6,%7}, {%8,%9}, {%0,%1,%2,%3};"
                 : "+f"(c[0]), "+f"(c[1]), "+f"(c[2]), "+f"(c[3])
                 : "r"(a[0]), "r"(a[1]), "r"(a[2]), "r"(a[3]),
                   "r"(b[0]), "r"(b[1]));
}

__device__ __forceinline__ uint32_t pack_bf2(float a, float b) {
    __nv_bfloat162 h = __floats2bfloat162_rn(a, b);
    return *(uint32_t*)&h;
}

// ---------------------------------------------------------------------------
// Split conversions: a = hi + lo (bf16). A rows: [hi, hi, lo]; W^T: [hi, lo, hi]
// ---------------------------------------------------------------------------
__global__ void split_rows(const float* __restrict__ in, __nv_bfloat16* __restrict__ out)
{
    size_t i = (size_t)blockIdx.x * blockDim.x + threadIdx.x;   // over ROWS*CH
    int r = (int)(i >> 10);
    int k = (int)(i & 1023);
    float a = in[i];
    __nv_bfloat16 hi = __float2bfloat16(a);
    __nv_bfloat16 lo = __float2bfloat16(a - __bfloat162float(hi));
    __nv_bfloat16* o = out + (size_t)r * K3;
    o[k] = hi; o[CH + k] = hi; o[2 * CH + k] = lo;
}

__global__ void split_wT(const float* __restrict__ W, __nv_bfloat16* __restrict__ Wt, int N)
{
    __shared__ float t[32][33];
    int n0 = blockIdx.x * 32, k0 = blockIdx.y * 32;
    int tx = threadIdx.x, ty = threadIdx.y;   // 32 x 8
    #pragma unroll
    for (int j = 0; j < 32; j += 8)
        t[ty + j][tx] = W[(size_t)(k0 + ty + j) * N + n0 + tx];
    __syncthreads();
    #pragma unroll
    for (int j = 0; j < 32; j += 8) {
        float a = t[tx][ty + j];
        __nv_bfloat16 hi = __float2bfloat16(a);
        __nv_bfloat16 lo = __float2bfloat16(a - __bfloat162float(hi));
        __nv_bfloat16* o = Wt + (size_t)(n0 + ty + j) * K3 + k0 + tx;
        o[0] = hi; o[CH] = lo; o[2 * CH] = hi;
    }
}

// ---------------------------------------------------------------------------
// mma.sync bf16 GEMM: C[M,N] = A[M,K3] * Bt[N,K3]^T (+bias), fp32 out.
// 128x128 CTA tile, BK=32, 8 warps (2x4), 4-stage cp.async ring, 1 sync/chunk.
// ---------------------------------------------------------------------------
#define BK   32
#define LDSW 40            // smem row stride in elems (32 + 8 pad)
#define NCHUNK (K3 / BK)   // 96
#define ASTG (128 * LDSW * 2)       // 10240 B per stage per operand
#define GSM_BYTES (8 * ASTG)        // 81920

template<bool BIAS>
__global__ __launch_bounds__(256)
void gemm_mma(const __nv_bfloat16* __restrict__ A, const __nv_bfloat16* __restrict__ Bt,
              const float* __restrict__ bias, float* __restrict__ C, int N)
{
    extern __shared__ __align__(128) char gsm[];
    const uint32_t sb = smem_u32(gsm);

    const int tid  = threadIdx.x;
    const int lane = tid & 31;
    const int warp = tid >> 5;
    const int wm   = warp >> 2;      // 0..1 : M
    const int wn   = warp & 3;       // 0..3 : N
    const int m0   = blockIdx.y * 128;
    const int n0   = blockIdx.x * 128;

    // cp.async mapping: thread handles 2 chunks each for A and B
    const int crow = tid >> 2;             // 0..63
    const int ckp  = (tid & 3) * 8;        // k offset in elems
    const uint32_t so0 = (uint32_t)(crow * LDSW + ckp) * 2;
    const uint32_t so1 = (uint32_t)((crow + 64) * LDSW + ckp) * 2;

    auto load = [&](int kc, int buf) {
        const uint32_t sA = sb + buf * ASTG;
        const uint32_t sB = sb + 4 * ASTG + buf * ASTG;
        const __nv_bfloat16* Ag = A + (size_t)(m0 + crow) * K3 + kc * BK + ckp;
        const __nv_bfloat16* Bg = Bt + (size_t)(n0 + crow) * K3 + kc * BK + ckp;
        CP_ASYNC16(sA + so0, Ag);
        CP_ASYNC16(sA + so1, Ag + (size_t)64 * K3);
        CP_ASYNC16(sB + so0, Bg);
        CP_ASYNC16(sB + so1, Bg + (size_t)64 * K3);
    };

    const int lmat = lane >> 3;
    const int lrow = lane & 7;
    const int a_row_base = wm * 64 + ((lmat & 1) << 3) + lrow;
    const int a_k_off    = (lmat >> 1) << 3;
    const int b_row_base = wn * 32 + ((lmat >> 1) << 3) + lrow;
    const int b_k_off    = (lmat & 1) << 3;

    float acc[4][4][4];
    #pragma unroll
    for (int i = 0; i < 4; i++)
        #pragma unroll
        for (int j = 0; j < 4; j++)
            #pragma unroll
            for (int q = 0; q < 4; q++) acc[i][j][q] = 0.0f;

    load(0, 0); CP_COMMIT();
    load(1, 1); CP_COMMIT();
    load(2, 2); CP_COMMIT();

    for (int t = 0; t < NCHUNK; t++) {
        const int buf = t & 3;
        CP_WAIT2();               // stage t complete (always 3 groups pending)
        __syncthreads();          // all warps done with stage t-1 compute
        if (t + 3 < NCHUNK) load(t + 3, (t + 3) & 3);
        CP_COMMIT();              // unconditional: keep group count invariant

        const uint32_t sA = sb + buf * ASTG;
        const uint32_t sB = sb + 4 * ASTG + buf * ASTG;
        #pragma unroll
        for (int ks = 0; ks < 2; ks++) {
            uint32_t a[4][4];
            #pragma unroll
            for (int mt = 0; mt < 4; mt++) {
                uint32_t ad = sA +
                    (uint32_t)((a_row_base + mt * 16) * LDSW + ks * 16 + a_k_off) * 2;
                ldsm_x4(a[mt][0], a[mt][1], a[mt][2], a[mt][3], ad);
            }
            uint32_t b[2][4];
            #pragma unroll
            for (int jj = 0; jj < 2; jj++) {
                uint32_t bd = sB +
                    (uint32_t)((b_row_base + jj * 16) * LDSW + ks * 16 + b_k_off) * 2;
                ldsm_x4(b[jj][0], b[jj][1], b[jj][2], b[jj][3], bd);
            }
            #pragma unroll
            for (int mt = 0; mt < 4; mt++)
                #pragma unroll
                for (int nf = 0; nf < 4; nf++)
                    mma16816(acc[mt][nf], a[mt], &b[nf >> 1][(nf & 1) * 2]);
        }
    }

    const int em = m0 + wm * 64 + (lane >> 2);
    const int en = n0 + wn * 32 + (lane & 3) * 2;
    #pragma unroll
    for (int mt = 0; mt < 4; mt++) {
        #pragma unroll
        for (int nf = 0; nf < 4; nf++) {
            float b0 = 0.f, b1 = 0.f;
            if (BIAS) { b0 = bias[en + nf * 8]; b1 = bias[en + nf * 8 + 1]; }
            float* c0 = C + (size_t)(em + mt * 16) * N + en + nf * 8;
            float* c1 = C + (size_t)(em + mt * 16 + 8) * N + en + nf * 8;
            *(float2*)c0 = make_float2(acc[mt][nf][0] + b0, acc[mt][nf][1] + b1);
            *(float2*)c1 = make_float2(acc[mt][nf][2] + b0, acc[mt][nf][3] + b1);
        }
    }
}

// ---------------------------------------------------------------------------
// Tensorized causal flash attention (mma.sync bf16 + 3-term split).
// Grid (SEQ/128, B*H); 8 warps; warp owns 16 q-rows x 64 keys / x 64 dims.
// Smem: Qs[128][136] (hi|lo), Ks[64][136] (hi|lo), Vs[128][72] (hi rows|lo rows).
// Epilogue writes split-bf16 proj input (g_as) directly.
// ---------------------------------------------------------------------------
#define LDQ 136
#define LDV 72
#define AT_BYTES ((128*LDQ + 64*LDQ + 128*LDV) * 2)   // 70656

__global__ __launch_bounds__(256, 2)
void flash_attn_mma(const float* __restrict__ qkv, __nv_bfloat16* __restrict__ as)
{
    extern __shared__ __align__(128) __nv_bfloat16 asm_[];
    __nv_bfloat16* Qs = asm_;
    __nv_bfloat16* Ks = Qs + 128 * LDQ;
    __nv_bfloat16* Vs = Ks + 64 * LDQ;
    const uint32_t sQ = smem_u32(Qs);
    const uint32_t sK = smem_u32(Ks);
    const uint32_t sV = smem_u32(Vs);

    const int tid  = threadIdx.x;
    const int lane = tid & 31;
    const int warp = tid >> 5;            // 0..7 -> 16 q rows each
    const int bh = blockIdx.y;
    const int b  = bh >> 4;
    const int h  = bh & 15;
    const int m0 = blockIdx.x * 128;

    const float* Qg = qkv + (size_t)b * SEQ * QKV_C + h * HDIM;
    const float* Kg = Qg + CH;
    const float* Vg = Qg + 2 * CH;

    // Load + split Q tile into smem: Qs[r][0..63]=hi, [64..127]=lo
    for (int i = tid; i < 128 * 16; i += 256) {
        int r  = i >> 4;
        int c4 = (i & 15) << 2;
        float4 q = *(const float4*)&Qg[(size_t)(m0 + r) * QKV_C + c4];
        float qa[4] = {q.x, q.y, q.z, q.w};
        #pragma unroll
        for (int j = 0; j < 4; j++) {
            __nv_bfloat16 hi = __float2bfloat16(qa[j]);
            Qs[r * LDQ + c4 + j]      = hi;
            Qs[r * LDQ + 64 + c4 + j] = __float2bfloat16(qa[j] - __bfloat162float(hi));
        }
    }

    // ldmatrix addressing
    const int lmat = lane >> 3;
    const int lrow = lane & 7;
    const int a_row = warp * 16 + ((lmat & 1) << 3) + lrow;   // A (Qs / non-trans)
    const int a_k   = (lmat >> 1) << 3;
    const int bs_rb = ((lmat >> 1) << 3) + lrow;              // B for S (Ks / non-trans)
    const int bs_k  = (lmat & 1) << 3;
    const int bv_r  = ((lmat & 1) << 3) + lrow;               // B for PV (Vs / trans)
    const int bv_c  = (lmat >> 1) << 3;

    float m_i[2] = {-1e30f, -1e30f};
    float l_i[2] = {0.0f, 0.0f};
    float oacc[8][4];
    #pragma unroll
    for (int nf = 0; nf < 8; nf++)
        #pragma unroll
        for (int q = 0; q < 4; q++) oacc[nf][q] = 0.0f;

    const int r0 = m0 + warp * 16 + (lane >> 2);   // abs q row (c0,c1)
    const int r1 = r0 + 8;                          // (c2,c3)

    const int ntiles = (m0 >> 6) + 2;
    for (int t = 0; t < ntiles; t++) {
        const int k0 = t << 6;

        __syncthreads();     // prior tile's MMAs done before overwrite
        for (int i = tid; i < 64 * 16; i += 256) {
            int r  = i >> 4;
            int c4 = (i & 15) << 2;
            size_t g = (size_t)(k0 + r) * QKV_C + c4;
            float4 kk = *(const float4*)&Kg[g];
            float4 vv = *(const float4*)&Vg[g];
            float ka[4] = {kk.x, kk.y, kk.z, kk.w};
            float va[4] = {vv.x, vv.y, vv.z, vv.w};
            #pragma unroll
            for (int j = 0; j < 4; j++) {
                __nv_bfloat16 khi = __float2bfloat16(ka[j]);
                Ks[r * LDQ + c4 + j]      = khi;
                Ks[r * LDQ + 64 + c4 + j] = __float2bfloat16(ka[j] - __bfloat162float(khi));
                __nv_bfloat16 vhi = __float2bfloat16(va[j]);
                Vs[r * LDV + c4 + j]        = vhi;
                Vs[(64 + r) * LDV + c4 + j] = __float2bfloat16(va[j] - __bfloat162float(vhi));
            }
        }
        __syncthreads();

        // ---- S = Q K^T (split: 12 k16 steps) ----
        float sacc[8][4];
        #pragma unroll
        for (int nf = 0; nf < 8; nf++)
            #pragma unroll
            for (int q = 0; q < 4; q++) sacc[nf][q] = 0.0f;

        #pragma unroll
        for (int s = 0; s < 12; s++) {
            const int qb = (s < 8) ? (s & 3) * 16 : 64 + (s & 3) * 16;
            const int kb = (s < 4) ? s * 16 : ((s < 8) ? 64 + (s - 4) * 16 : (s - 8) * 16);
            uint32_t a[4];
            ldsm_x4(a[0], a[1], a[2], a[3],
                    sQ + (uint32_t)(a_row * LDQ + qb + a_k) * 2);
            #pragma unroll
            for (int nt = 0; nt < 4; nt++) {
                uint32_t bb[4];
                ldsm_x4(bb[0], bb[1], bb[2], bb[3],
                        sK + (uint32_t)((nt * 16 + bs_rb) * LDQ + kb + bs_k) * 2);
                mma16816(sacc[nt * 2],     a, &bb[0]);
                mma16816(sacc[nt * 2 + 1], a, &bb[2]);
            }
        }

        // ---- softmax (register, online) ----
        const bool need_mask = (k0 + 63 > m0 + warp * 16);
        float mx0 = -1e30f, mx1 = -1e30f;
        #pragma unroll
        for (int nf = 0; nf < 8; nf++) {
            const int cb = k0 + nf * 8 + ((lane & 3) << 1);
            float v0 = sacc[nf][0] * 0.125f;
            float v1 = sacc[nf][1] * 0.125f;
            float v2 = sacc[nf][2] * 0.125f;
            float v3 = sacc[nf][3] * 0.125f;
            if (need_mask) {
                if (cb     > r0) v0 = -1e30f;
                if (cb + 1 > r0) v1 = -1e30f;
                if (cb     > r1) v2 = -1e30f;
                if (cb + 1 > r1) v3 = -1e30f;
            }
            sacc[nf][0] = v0; sacc[nf][1] = v1;
            sacc[nf][2] = v2; sacc[nf][3] = v3;
            mx0 = fmaxf(mx0, fmaxf(v0, v1));
            mx1 = fmaxf(mx1, fmaxf(v2, v3));
        }
        mx0 = fmaxf(mx0, __shfl_xor_sync(0xffffffffu, mx0, 1));
        mx0 = fmaxf(mx0, __shfl_xor_sync(0xffffffffu, mx0, 2));
        mx1 = fmaxf(mx1, __shfl_xor_sync(0xffffffffu, mx1, 1));
        mx1 = fmaxf(mx1, __shfl_xor_sync(0xffffffffu, mx1, 2));

        const float mn0 = fmaxf(m_i[0], mx0);
        const float mn1 = fmaxf(m_i[1], mx1);
        const float cr0 = __expf(m_i[0] - mn0);
        const float cr1 = __expf(m_i[1] - mn1);
        m_i[0] = mn0; m_i[1] = mn1;

        float sm0 = 0.f, sm1 = 0.f;
        #pragma unroll
        for (int nf = 0; nf < 8; nf++) {
            float p0 = __expf(sacc[nf][0] - mn0);
            float p1 = __expf(sacc[nf][1] - mn0);
            float p2 = __expf(sacc[nf][2] - mn1);
            float p3 = __expf(sacc[nf][3] - mn1);
            sacc[nf][0] = p0; sacc[nf][1] = p1;
            sacc[nf][2] = p2; sacc[nf][3] = p3;
            sm0 += p0 + p1;  sm1 += p2 + p3;
        }
        sm0 += __shfl_xor_sync(0xffffffffu, sm0, 1);
        sm0 += __shfl_xor_sync(0xffffffffu, sm0, 2);
        sm1 += __shfl_xor_sync(0xffffffffu, sm1, 1);
        sm1 += __shfl_xor_sync(0xffffffffu, sm1, 2);
        l_i[0] = l_i[0] * cr0 + sm0;
        l_i[1] = l_i[1] * cr1 + sm1;
        #pragma unroll
        for (int nf = 0; nf < 8; nf++) {
            oacc[nf][0] *= cr0; oacc[nf][1] *= cr0;
            oacc[nf][2] *= cr1; oacc[nf][3] *= cr1;
        }

        // ---- O += P V (split: 12 k16 steps; A frags built from sacc) ----
        #pragma unroll
        for (int s = 0; s < 12; s++) {
            const int ks = s & 3;
            const int kb = (s < 4) ? s * 16 : ((s < 8) ? 64 + (s - 4) * 16 : (s - 8) * 16);
            uint32_t pa[4];
            if (s < 8) {   // P_hi
                pa[0] = pack_bf2(sacc[2 * ks][0],     sacc[2 * ks][1]);
                pa[1] = pack_bf2(sacc[2 * ks][2],     sacc[2 * ks][3]);
                pa[2] = pack_bf2(sacc[2 * ks + 1][0], sacc[2 * ks + 1][1]);
                pa[3] = pack_bf2(sacc[2 * ks + 1][2], sacc[2 * ks + 1][3]);
            } else {       // P_lo = p - bf16(p)
                #pragma unroll
                for (int half = 0; half < 2; half++) {
                    const int nf = 2 * ks + half;
                    uint32_t h01 = pack_bf2(sacc[nf][0], sacc[nf][1]);
                    uint32_t h23 = pack_bf2(sacc[nf][2], sacc[nf][3]);
                    __nv_bfloat162 b01 = *(__nv_bfloat162*)&h01;
                    __nv_bfloat162 b23 = *(__nv_bfloat162*)&h23;
                    pa[half * 2]     = pack_bf2(sacc[nf][0] - __low2float(b01),
                                                sacc[nf][1] - __high2float(b01));
                    pa[half * 2 + 1] = pack_bf2(sacc[nf][2] - __low2float(b23),
                                                sacc[nf][3] - __high2float(b23));
                }
            }
            #pragma unroll
            for (int nt = 0; nt < 4; nt++) {
                uint32_t bb[4];
                ldsm_x4t(bb[0], bb[1], bb[2], bb[3],
                         sV + (uint32_t)((kb + bv_r) * LDV + nt * 16 + bv_c) * 2);
                mma16816(oacc[nt * 2],     pa, &bb[0]);
                mma16816(oacc[nt * 2 + 1], pa, &bb[2]);
            }
        }
    }

    // ---- epilogue: normalize + fused split write to g_as ----
    const float inv0 = 1.0f / l_i[0];
    const float inv1 = 1.0f / l_i[1];
    const size_t row0 = (size_t)(b * SEQ + r0) * K3;
    const size_t row1 = (size_t)(b * SEQ + r1) * K3;
    #pragma unroll
    for (int nf = 0; nf < 8; nf++) {
        const int col = h * HDIM + nf * 8 + ((lane & 3) << 1);
        float v0 = oacc[nf][0] * inv0, v1 = oacc[nf][1] * inv0;
        float v2 = oacc[nf][2] * inv1, v3 = oacc[nf][3] * inv1;

        uint32_t hiA = pack_bf2(v0, v1);
        __nv_bfloat162 hA = *(__nv_bfloat162*)&hiA;
        uint32_t loA = pack_bf2(v0 - __low2float(hA), v1 - __high2float(hA));
        uint32_t hiB = pack_bf2(v2, v3);
        __nv_bfloat162 hB = *(__nv_bfloat162*)&hiB;
        uint32_t loB = pack_bf2(v2 - __low2float(hB), v3 - __high2float(hB));

        uint32_t* pA = (uint32_t*)(as + row0 + col);
        pA[0]            = hiA;
        *(uint32_t*)(as + row0 + CH + col)     = hiA;
        *(uint32_t*)(as + row0 + 2 * CH + col) = loA;
        uint32_t* pB = (uint32_t*)(as + row1 + col);
        pB[0]            = hiB;
        *(uint32_t*)(as + row1 + CH + col)     = hiB;
        *(uint32_t*)(as + row1 + 2 * CH + col) = loB;
    }
}

// ---------------------------------------------------------------------------
extern "C" void kernel_launch(void* const* d_in, const int* in_sizes, int n_in,
                              void* d_out, int out_size)
{
    const float* x     = (const float*)d_in[0];
    const float* Wqkv  = (const float*)d_in[2];
    const float* Wproj = (const float*)d_in[3];
    const float* bproj = (const float*)d_in[4];
    float* out = (float*)d_out;

    void *p_qkv, *p_xs, *p_as, *p_wqkt, *p_wpt;
    cudaGetSymbolAddress(&p_qkv, g_qkv);
    cudaGetSymbolAddress(&p_xs, g_xs);
    cudaGetSymbolAddress(&p_as, g_as);
    cudaGetSymbolAddress(&p_wqkt, g_wqkt);
    cudaGetSymbolAddress(&p_wpt, g_wpt);
    float* qkv  = (float*)p_qkv;
    __nv_bfloat16* xs   = (__nv_bfloat16*)p_xs;
    __nv_bfloat16* as   = (__nv_bfloat16*)p_as;
    __nv_bfloat16* wqkt = (__nv_bfloat16*)p_wqkt;
    __nv_bfloat16* wpt  = (__nv_bfloat16*)p_wpt;

    cudaFuncSetAttribute(gemm_mma<false>, cudaFuncAttributeMaxDynamicSharedMemorySize,
                         GSM_BYTES);
    cudaFuncSetAttribute(gemm_mma<true>, cudaFuncAttributeMaxDynamicSharedMemorySize,
                         GSM_BYTES);
    cudaFuncSetAttribute(flash_attn_mma, cudaFuncAttributeMaxDynamicSharedMemorySize,
                         AT_BYTES);

    // conversions
    split_rows<<<(ROWS * CH) / 256, 256>>>(x, xs);
    dim3 wt1(QKV_C / 32, CH / 32);
    split_wT<<<wt1, dim3(32, 8)>>>(Wqkv, wqkt, QKV_C);
    dim3 wt2(CH / 32, CH / 32);
    split_wT<<<wt2, dim3(32, 8)>>>(Wproj, wpt, CH);

    // 1) qkv = x @ W_qkv
    dim3 g1(QKV_C / 128, ROWS / 128);
    gemm_mma<false><<<g1, 256, GSM_BYTES>>>(xs, wqkt, nullptr, qkv, QKV_C);

    // 2) causal flash attention -> split proj input (fused)
    dim3 g2(SEQ / 128, BATCH * HEADS);
    flash_attn_mma<<<g2, 256, AT_BYTES>>>(qkv, as);

    // 3) out = attn @ W_proj + b
    dim3 g3(CH / 128, ROWS / 128);
    gemm_mma<true><<<g3, 256, GSM_BYTES>>>(as, wpt, bproj, out, CH);
}

// round 9
// speedup vs baseline: 2.7856x; 1.5952x over previous
#include <cuda_runtime.h>
#include <cuda_fp16.h>
#include <cstdint>

// ---------------------------------------------------------------------------
// AttentionRAR: x -> qkv GEMM -> causal flash attention -> proj GEMM (+bias)
// B=4, N=2048, C=1024, H=16, D=64
// All matmuls on mma.sync fp16 with 2-term one-sided precision split:
//   a*b ~= (a_hi + a_lo) * b_hi   (error a*b_lo ~ 2^-11 rel per stage)
// K folded 1024 -> 2048 on GEMMs; attention uses Q/P split, K/V hi-only.
// ---------------------------------------------------------------------------

#define BATCH 4
#define SEQ   2048
#define CH    1024
#define HEADS 16
#define HDIM  64
#define ROWS  (BATCH * SEQ)       // 8192
#define QKV_C (3 * CH)            // 3072
#define K2    (2 * CH)            // split K = 2048

// Scratch (static device globals)
__device__ __align__(1024) float g_qkv[(size_t)ROWS * QKV_C];
__device__ __align__(1024) __half g_xs[(size_t)ROWS * K2];
__device__ __align__(1024) __half g_as[(size_t)ROWS * K2];
__device__ __align__(1024) __half g_wqkt[(size_t)QKV_C * K2];
__device__ __align__(1024) __half g_wpt[(size_t)CH * K2];

// ======================= helpers ===========================================
__device__ __forceinline__ uint32_t smem_u32(const void* p) {
    uint32_t a;
    asm("{ .reg .u64 t; cvta.to.shared.u64 t, %1; cvt.u32.u64 %0, t; }"
        : "=r"(a) : "l"(p));
    return a;
}

#define CP_ASYNC16(sm, gp) \
    asm volatile("cp.async.cg.shared.global [%0], [%1], 16;" :: "r"(sm), "l"(gp))
#define CP_COMMIT() asm volatile("cp.async.commit_group;" ::: "memory")
#define CP_WAIT2()  asm volatile("cp.async.wait_group 2;" ::: "memory")

__device__ __forceinline__ void ldsm_x4(uint32_t& r0, uint32_t& r1,
                                        uint32_t& r2, uint32_t& r3, uint32_t a) {
    asm volatile("ldmatrix.sync.aligned.m8n8.x4.shared.b16 {%0,%1,%2,%3}, [%4];"
                 : "=r"(r0), "=r"(r1), "=r"(r2), "=r"(r3) : "r"(a));
}
__device__ __forceinline__ void ldsm_x4t(uint32_t& r0, uint32_t& r1,
                                         uint32_t& r2, uint32_t& r3, uint32_t a) {
    asm volatile("ldmatrix.sync.aligned.m8n8.x4.trans.shared.b16 {%0,%1,%2,%3}, [%4];"
                 : "=r"(r0), "=r"(r1), "=r"(r2), "=r"(r3) : "r"(a));
}

__device__ __forceinline__ void mma16816(float* c, const uint32_t* a,
                                         const uint32_t* b) {
    asm volatile("mma.sync.aligned.m16n8k16.row.col.f32.f16.f16.f32 "
                 "{%0,%1,%2,%3}, {%4,%5,%6,%7}, {%8,%9}, {%0,%1,%2,%3};"
                 : "+f"(c[0]), "+f"(c[1]), "+f"(c[2]), "+f"(c[3])
                 : "r"(a[0]), "r"(a[1]), "r"(a[2]), "r"(a[3]),
                   "r"(b[0]), "r"(b[1]));
}

__device__ __forceinline__ uint32_t pack_h2(float a, float b) {
    __half2 h = __floats2half2_rn(a, b);
    return *(uint32_t*)&h;
}

// ---------------------------------------------------------------------------
// Split conversions (fp16): activations a = hi + lo -> [hi | lo];
// weights^T -> [hi | hi] (duplicated hi).
// ---------------------------------------------------------------------------
__global__ void split_rows(const float* __restrict__ in, __half* __restrict__ out)
{
    size_t i = (size_t)blockIdx.x * blockDim.x + threadIdx.x;   // over ROWS*CH
    int r = (int)(i >> 10);
    int k = (int)(i & 1023);
    float a = in[i];
    __half hi = __float2half(a);
    __half lo = __float2half(a - __half2float(hi));
    __half* o = out + (size_t)r * K2;
    o[k] = hi; o[CH + k] = lo;
}

// W [K=CH, N] fp32 -> Wt [N, K2]: [0,CH)=hi, [CH,2CH)=hi
__global__ void split_wT(const float* __restrict__ W, __half* __restrict__ Wt, int N)
{
    __shared__ float t[32][33];
    int n0 = blockIdx.x * 32, k0 = blockIdx.y * 32;
    int tx = threadIdx.x, ty = threadIdx.y;   // 32 x 8
    #pragma unroll
    for (int j = 0; j < 32; j += 8)
        t[ty + j][tx] = W[(size_t)(k0 + ty + j) * N + n0 + tx];
    __syncthreads();
    #pragma unroll
    for (int j = 0; j < 32; j += 8) {
        float a = t[tx][ty + j];
        __half hi = __float2half(a);
        __half* o = Wt + (size_t)(n0 + ty + j) * K2 + k0 + tx;
        o[0] = hi; o[CH] = hi;
    }
}

// ---------------------------------------------------------------------------
// mma.sync fp16 GEMM: C[M,N] = A[M,K2] * Bt[N,K2]^T (+bias), fp32 out.
// 128x128 CTA tile, BK=32, 8 warps (2x4), 4-stage cp.async ring.
// ---------------------------------------------------------------------------
#define BK   32
#define LDSW 40
#define NCHUNK (K2 / BK)            // 64
#define ASTG (128 * LDSW * 2)       // 10240 B per stage per operand
#define GSM_BYTES (8 * ASTG)        // 81920

template<bool BIAS>
__global__ __launch_bounds__(256)
void gemm_mma(const __half* __restrict__ A, const __half* __restrict__ Bt,
              const float* __restrict__ bias, float* __restrict__ C, int N)
{
    extern __shared__ __align__(128) char gsm[];
    const uint32_t sb = smem_u32(gsm);

    const int tid  = threadIdx.x;
    const int lane = tid & 31;
    const int warp = tid >> 5;
    const int wm   = warp >> 2;
    const int wn   = warp & 3;
    const int m0   = blockIdx.y * 128;
    const int n0   = blockIdx.x * 128;

    const int crow = tid >> 2;
    const int ckp  = (tid & 3) * 8;
    const uint32_t so0 = (uint32_t)(crow * LDSW + ckp) * 2;
    const uint32_t so1 = (uint32_t)((crow + 64) * LDSW + ckp) * 2;

    auto load = [&](int kc, int buf) {
        const uint32_t sA = sb + buf * ASTG;
        const uint32_t sB = sb + 4 * ASTG + buf * ASTG;
        const __half* Ag = A + (size_t)(m0 + crow) * K2 + kc * BK + ckp;
        const __half* Bg = Bt + (size_t)(n0 + crow) * K2 + kc * BK + ckp;
        CP_ASYNC16(sA + so0, Ag);
        CP_ASYNC16(sA + so1, Ag + (size_t)64 * K2);
        CP_ASYNC16(sB + so0, Bg);
        CP_ASYNC16(sB + so1, Bg + (size_t)64 * K2);
    };

    const int lmat = lane >> 3;
    const int lrow = lane & 7;
    const int a_row_base = wm * 64 + ((lmat & 1) << 3) + lrow;
    const int a_k_off    = (lmat >> 1) << 3;
    const int b_row_base = wn * 32 + ((lmat >> 1) << 3) + lrow;
    const int b_k_off    = (lmat & 1) << 3;

    float acc[4][4][4];
    #pragma unroll
    for (int i = 0; i < 4; i++)
        #pragma unroll
        for (int j = 0; j < 4; j++)
            #pragma unroll
            for (int q = 0; q < 4; q++) acc[i][j][q] = 0.0f;

    load(0, 0); CP_COMMIT();
    load(1, 1); CP_COMMIT();
    load(2, 2); CP_COMMIT();

    for (int t = 0; t < NCHUNK; t++) {
        const int buf = t & 3;
        CP_WAIT2();
        __syncthreads();
        if (t + 3 < NCHUNK) load(t + 3, (t + 3) & 3);
        CP_COMMIT();

        const uint32_t sA = sb + buf * ASTG;
        const uint32_t sB = sb + 4 * ASTG + buf * ASTG;
        #pragma unroll
        for (int ks = 0; ks < 2; ks++) {
            uint32_t a[4][4];
            #pragma unroll
            for (int mt = 0; mt < 4; mt++) {
                uint32_t ad = sA +
                    (uint32_t)((a_row_base + mt * 16) * LDSW + ks * 16 + a_k_off) * 2;
                ldsm_x4(a[mt][0], a[mt][1], a[mt][2], a[mt][3], ad);
            }
            uint32_t b[2][4];
            #pragma unroll
            for (int jj = 0; jj < 2; jj++) {
                uint32_t bd = sB +
                    (uint32_t)((b_row_base + jj * 16) * LDSW + ks * 16 + b_k_off) * 2;
                ldsm_x4(b[jj][0], b[jj][1], b[jj][2], b[jj][3], bd);
            }
            #pragma unroll
            for (int mt = 0; mt < 4; mt++)
                #pragma unroll
                for (int nf = 0; nf < 4; nf++)
                    mma16816(acc[mt][nf], a[mt], &b[nf >> 1][(nf & 1) * 2]);
        }
    }

    const int em = m0 + wm * 64 + (lane >> 2);
    const int en = n0 + wn * 32 + (lane & 3) * 2;
    #pragma unroll
    for (int mt = 0; mt < 4; mt++) {
        #pragma unroll
        for (int nf = 0; nf < 4; nf++) {
            float b0 = 0.f, b1 = 0.f;
            if (BIAS) { b0 = bias[en + nf * 8]; b1 = bias[en + nf * 8 + 1]; }
            float* c0 = C + (size_t)(em + mt * 16) * N + en + nf * 8;
            float* c1 = C + (size_t)(em + mt * 16 + 8) * N + en + nf * 8;
            *(float2*)c0 = make_float2(acc[mt][nf][0] + b0, acc[mt][nf][1] + b1);
            *(float2*)c1 = make_float2(acc[mt][nf][2] + b0, acc[mt][nf][3] + b1);
        }
    }
}

// ---------------------------------------------------------------------------
// Tensorized causal flash attention (mma.sync fp16, 2-term split).
// Q split [hi|lo] in smem; K, V hi-only. P split in registers.
// Grid (SEQ/128, B*H); 8 warps; warp owns 16 q-rows.
// Epilogue writes split-fp16 proj input (g_as) directly.
// ---------------------------------------------------------------------------
#define LDQ 136
#define LDK 72
#define LDV 72
#define AT_BYTES ((128*LDQ + 64*LDK + 64*LDV) * 2)   // 53248

__global__ __launch_bounds__(256, 2)
void flash_attn_mma(const float* __restrict__ qkv, __half* __restrict__ as)
{
    extern __shared__ __align__(128) __half hsm[];
    __half* Qs = hsm;                    // [128][136]  (hi 0..63 | lo 64..127)
    __half* Ks = Qs + 128 * LDQ;         // [64][72]    hi only
    __half* Vs = Ks + 64 * LDK;          // [64][72]    hi only
    const uint32_t sQ = smem_u32(Qs);
    const uint32_t sK = smem_u32(Ks);
    const uint32_t sV = smem_u32(Vs);

    const int tid  = threadIdx.x;
    const int lane = tid & 31;
    const int warp = tid >> 5;
    const int bh = blockIdx.y;
    const int b  = bh >> 4;
    const int h  = bh & 15;
    const int m0 = blockIdx.x * 128;

    const float* Qg = qkv + (size_t)b * SEQ * QKV_C + h * HDIM;
    const float* Kg = Qg + CH;
    const float* Vg = Qg + 2 * CH;

    // Load + split Q tile
    for (int i = tid; i < 128 * 16; i += 256) {
        int r  = i >> 4;
        int c4 = (i & 15) << 2;
        float4 q = *(const float4*)&Qg[(size_t)(m0 + r) * QKV_C + c4];
        float qa[4] = {q.x, q.y, q.z, q.w};
        #pragma unroll
        for (int j = 0; j < 4; j++) {
            __half hi = __float2half(qa[j]);
            Qs[r * LDQ + c4 + j]      = hi;
            Qs[r * LDQ + 64 + c4 + j] = __float2half(qa[j] - __half2float(hi));
        }
    }

    const int lmat = lane >> 3;
    const int lrow = lane & 7;
    const int a_row = warp * 16 + ((lmat & 1) << 3) + lrow;   // A (Qs)
    const int a_k   = (lmat >> 1) << 3;
    const int bs_rb = ((lmat >> 1) << 3) + lrow;              // B for S (Ks)
    const int bs_k  = (lmat & 1) << 3;
    const int bv_r  = ((lmat & 1) << 3) + lrow;               // B for PV (Vs, trans)
    const int bv_c  = (lmat >> 1) << 3;

    float m_i[2] = {-1e30f, -1e30f};
    float l_i[2] = {0.0f, 0.0f};
    float oacc[8][4];
    #pragma unroll
    for (int nf = 0; nf < 8; nf++)
        #pragma unroll
        for (int q = 0; q < 4; q++) oacc[nf][q] = 0.0f;

    const int r0 = m0 + warp * 16 + (lane >> 2);
    const int r1 = r0 + 8;

    const int ntiles = (m0 >> 6) + 2;
    for (int t = 0; t < ntiles; t++) {
        const int k0 = t << 6;

        __syncthreads();
        for (int i = tid; i < 64 * 16; i += 256) {
            int r  = i >> 4;
            int c4 = (i & 15) << 2;
            size_t g = (size_t)(k0 + r) * QKV_C + c4;
            float4 kk = *(const float4*)&Kg[g];
            float4 vv = *(const float4*)&Vg[g];
            Ks[r * LDK + c4 + 0] = __float2half(kk.x);
            Ks[r * LDK + c4 + 1] = __float2half(kk.y);
            Ks[r * LDK + c4 + 2] = __float2half(kk.z);
            Ks[r * LDK + c4 + 3] = __float2half(kk.w);
            Vs[r * LDV + c4 + 0] = __float2half(vv.x);
            Vs[r * LDV + c4 + 1] = __float2half(vv.y);
            Vs[r * LDV + c4 + 2] = __float2half(vv.z);
            Vs[r * LDV + c4 + 3] = __float2half(vv.w);
        }
        __syncthreads();

        // ---- S = (Q_hi + Q_lo) K_hi^T : 8 k16 steps ----
        float sacc[8][4];
        #pragma unroll
        for (int nf = 0; nf < 8; nf++)
            #pragma unroll
            for (int q = 0; q < 4; q++) sacc[nf][q] = 0.0f;

        #pragma unroll
        for (int s = 0; s < 8; s++) {
            const int qb = (s < 4) ? (s & 3) * 16 : 64 + (s & 3) * 16;
            const int kb = (s & 3) * 16;
            uint32_t a[4];
            ldsm_x4(a[0], a[1], a[2], a[3],
                    sQ + (uint32_t)(a_row * LDQ + qb + a_k) * 2);
            #pragma unroll
            for (int nt = 0; nt < 4; nt++) {
                uint32_t bb[4];
                ldsm_x4(bb[0], bb[1], bb[2], bb[3],
                        sK + (uint32_t)((nt * 16 + bs_rb) * LDK + kb + bs_k) * 2);
                mma16816(sacc[nt * 2],     a, &bb[0]);
                mma16816(sacc[nt * 2 + 1], a, &bb[2]);
            }
        }

        // ---- softmax (register, online) ----
        const bool need_mask = (k0 + 63 > m0 + warp * 16);
        float mx0 = -1e30f, mx1 = -1e30f;
        #pragma unroll
        for (int nf = 0; nf < 8; nf++) {
            const int cb = k0 + nf * 8 + ((lane & 3) << 1);
            float v0 = sacc[nf][0] * 0.125f;
            float v1 = sacc[nf][1] * 0.125f;
            float v2 = sacc[nf][2] * 0.125f;
            float v3 = sacc[nf][3] * 0.125f;
            if (need_mask) {
                if (cb     > r0) v0 = -1e30f;
                if (cb + 1 > r0) v1 = -1e30f;
                if (cb     > r1) v2 = -1e30f;
                if (cb + 1 > r1) v3 = -1e30f;
            }
            sacc[nf][0] = v0; sacc[nf][1] = v1;
            sacc[nf][2] = v2; sacc[nf][3] = v3;
            mx0 = fmaxf(mx0, fmaxf(v0, v1));
            mx1 = fmaxf(mx1, fmaxf(v2, v3));
        }
        mx0 = fmaxf(mx0, __shfl_xor_sync(0xffffffffu, mx0, 1));
        mx0 = fmaxf(mx0, __shfl_xor_sync(0xffffffffu, mx0, 2));
        mx1 = fmaxf(mx1, __shfl_xor_sync(0xffffffffu, mx1, 1));
        mx1 = fmaxf(mx1, __shfl_xor_sync(0xffffffffu, mx1, 2));

        const float mn0 = fmaxf(m_i[0], mx0);
        const float mn1 = fmaxf(m_i[1], mx1);
        const float cr0 = __expf(m_i[0] - mn0);
        const float cr1 = __expf(m_i[1] - mn1);
        m_i[0] = mn0; m_i[1] = mn1;

        float sm0 = 0.f, sm1 = 0.f;
        #pragma unroll
        for (int nf = 0; nf < 8; nf++) {
            float p0 = __expf(sacc[nf][0] - mn0);
            float p1 = __expf(sacc[nf][1] - mn0);
            float p2 = __expf(sacc[nf][2] - mn1);
            float p3 = __expf(sacc[nf][3] - mn1);
            sacc[nf][0] = p0; sacc[nf][1] = p1;
            sacc[nf][2] = p2; sacc[nf][3] = p3;
            sm0 += p0 + p1;  sm1 += p2 + p3;
        }
        sm0 += __shfl_xor_sync(0xffffffffu, sm0, 1);
        sm0 += __shfl_xor_sync(0xffffffffu, sm0, 2);
        sm1 += __shfl_xor_sync(0xffffffffu, sm1, 1);
        sm1 += __shfl_xor_sync(0xffffffffu, sm1, 2);
        l_i[0] = l_i[0] * cr0 + sm0;
        l_i[1] = l_i[1] * cr1 + sm1;
        #pragma unroll
        for (int nf = 0; nf < 8; nf++) {
            oacc[nf][0] *= cr0; oacc[nf][1] *= cr0;
            oacc[nf][2] *= cr1; oacc[nf][3] *= cr1;
        }

        // ---- O += (P_hi + P_lo) V_hi : 8 k16 steps ----
        #pragma unroll
        for (int s = 0; s < 8; s++) {
            const int ks = s & 3;
            const int kb = ks * 16;
            uint32_t pa[4];
            if (s < 4) {   // P_hi
                pa[0] = pack_h2(sacc[2 * ks][0],     sacc[2 * ks][1]);
                pa[1] = pack_h2(sacc[2 * ks][2],     sacc[2 * ks][3]);
                pa[2] = pack_h2(sacc[2 * ks + 1][0], sacc[2 * ks + 1][1]);
                pa[3] = pack_h2(sacc[2 * ks + 1][2], sacc[2 * ks + 1][3]);
            } else {       // P_lo = p - fp16(p)
                #pragma unroll
                for (int half_i = 0; half_i < 2; half_i++) {
                    const int nf = 2 * ks + half_i;
                    uint32_t h01 = pack_h2(sacc[nf][0], sacc[nf][1]);
                    uint32_t h23 = pack_h2(sacc[nf][2], sacc[nf][3]);
                    __half2 b01 = *(__half2*)&h01;
                    __half2 b23 = *(__half2*)&h23;
                    pa[half_i * 2]     = pack_h2(sacc[nf][0] - __low2float(b01),
                                                 sacc[nf][1] - __high2float(b01));
                    pa[half_i * 2 + 1] = pack_h2(sacc[nf][2] - __low2float(b23),
                                                 sacc[nf][3] - __high2float(b23));
                }
            }
            #pragma unroll
            for (int nt = 0; nt < 4; nt++) {
                uint32_t bb[4];
                ldsm_x4t(bb[0], bb[1], bb[2], bb[3],
                         sV + (uint32_t)((kb + bv_r) * LDV + nt * 16 + bv_c) * 2);
                mma16816(oacc[nt * 2],     pa, &bb[0]);
                mma16816(oacc[nt * 2 + 1], pa, &bb[2]);
            }
        }
    }

    // ---- epilogue: normalize + fused split write to g_as [hi | lo] ----
    const float inv0 = 1.0f / l_i[0];
    const float inv1 = 1.0f / l_i[1];
    const size_t row0 = (size_t)(b * SEQ + r0) * K2;
    const size_t row1 = (size_t)(b * SEQ + r1) * K2;
    #pragma unroll
    for (int nf = 0; nf < 8; nf++) {
        const int col = h * HDIM + nf * 8 + ((lane & 3) << 1);
        float v0 = oacc[nf][0] * inv0, v1 = oacc[nf][1] * inv0;
        float v2 = oacc[nf][2] * inv1, v3 = oacc[nf][3] * inv1;

        uint32_t hiA = pack_h2(v0, v1);
        __half2 hA = *(__half2*)&hiA;
        uint32_t loA = pack_h2(v0 - __low2float(hA), v1 - __high2float(hA));
        uint32_t hiB = pack_h2(v2, v3);
        __half2 hB = *(__half2*)&hiB;
        uint32_t loB = pack_h2(v2 - __low2float(hB), v3 - __high2float(hB));

        *(uint32_t*)(as + row0 + col)      = hiA;
        *(uint32_t*)(as + row0 + CH + col) = loA;
        *(uint32_t*)(as + row1 + col)      = hiB;
        *(uint32_t*)(as + row1 + CH + col) = loB;
    }
}

// ---------------------------------------------------------------------------
extern "C" void kernel_launch(void* const* d_in, const int* in_sizes, int n_in,
                              void* d_out, int out_size)
{
    const float* x     = (const float*)d_in[0];
    const float* Wqkv  = (const float*)d_in[2];
    const float* Wproj = (const float*)d_in[3];
    const float* bproj = (const float*)d_in[4];
    float* out = (float*)d_out;

    void *p_qkv, *p_xs, *p_as, *p_wqkt, *p_wpt;
    cudaGetSymbolAddress(&p_qkv, g_qkv);
    cudaGetSymbolAddress(&p_xs, g_xs);
    cudaGetSymbolAddress(&p_as, g_as);
    cudaGetSymbolAddress(&p_wqkt, g_wqkt);
    cudaGetSymbolAddress(&p_wpt, g_wpt);
    float* qkv = (float*)p_qkv;
    __half* xs   = (__half*)p_xs;
    __half* as   = (__half*)p_as;
    __half* wqkt = (__half*)p_wqkt;
    __half* wpt  = (__half*)p_wpt;

    cudaFuncSetAttribute(gemm_mma<false>, cudaFuncAttributeMaxDynamicSharedMemorySize,
                         GSM_BYTES);
    cudaFuncSetAttribute(gemm_mma<true>, cudaFuncAttributeMaxDynamicSharedMemorySize,
                         GSM_BYTES);
    cudaFuncSetAttribute(flash_attn_mma, cudaFuncAttributeMaxDynamicSharedMemorySize,
                         AT_BYTES);

    // conversions
    split_rows<<<(ROWS * CH) / 256, 256>>>(x, xs);
    dim3 wt1(QKV_C / 32, CH / 32);
    split_wT<<<wt1, dim3(32, 8)>>>(Wqkv, wqkt, QKV_C);
    dim3 wt2(CH / 32, CH / 32);
    split_wT<<<wt2, dim3(32, 8)>>>(Wproj, wpt, CH);

    // 1) qkv = x @ W_qkv
    dim3 g1(QKV_C / 128, ROWS / 128);
    gemm_mma<false><<<g1, 256, GSM_BYTES>>>(xs, wqkt, nullptr, qkv, QKV_C);

    // 2) causal flash attention -> split proj input (fused)
    dim3 g2(SEQ / 128, BATCH * HEADS);
    flash_attn_mma<<<g2, 256, AT_BYTES>>>(qkv, as);

    // 3) out = attn @ W_proj + b
    dim3 g3(CH / 128, ROWS / 128);
    gemm_mma<true><<<g3, 256, GSM_BYTES>>>(as, wpt, bproj, out, CH);
}

// round 10
// speedup vs baseline: 3.2074x; 1.1514x over previous
#include <cuda_runtime.h>
#include <cuda_fp16.h>
#include <cstdint>

// ---------------------------------------------------------------------------
// AttentionRAR: x -> qkv GEMM -> causal flash attention -> proj GEMM (+bias)
// B=4, N=2048, C=1024, H=16, D=64
// All matmuls on mma.sync fp16, 2-term one-sided split: a*b ~= (a_hi+a_lo)*b_hi
// gemm0 epilogue emits fp16 qkv (hi) + Q lo directly for attention.
// ---------------------------------------------------------------------------

#define BATCH 4
#define SEQ   2048
#define CH    1024
#define HEADS 16
#define HDIM  64
#define ROWS  (BATCH * SEQ)       // 8192
#define QKV_C (3 * CH)            // 3072
#define K2    (2 * CH)            // split K = 2048

// Scratch
__device__ __align__(1024) __half g_qh [(size_t)ROWS * QKV_C];  // qkv hi (fp16)
__device__ __align__(1024) __half g_qlo[(size_t)ROWS * CH];     // q lo   (fp16)
__device__ __align__(1024) __half g_xs [(size_t)ROWS * K2];
__device__ __align__(1024) __half g_as [(size_t)ROWS * K2];
__device__ __align__(1024) __half g_wqkt[(size_t)QKV_C * K2];
__device__ __align__(1024) __half g_wpt [(size_t)CH * K2];

// ======================= helpers ===========================================
__device__ __forceinline__ uint32_t smem_u32(const void* p) {
    uint32_t a;
    asm("{ .reg .u64 t; cvta.to.shared.u64 t, %1; cvt.u32.u64 %0, t; }"
        : "=r"(a) : "l"(p));
    return a;
}

#define CP_ASYNC16(sm, gp) \
    asm volatile("cp.async.cg.shared.global [%0], [%1], 16;" :: "r"(sm), "l"(gp))
#define CP_COMMIT() asm volatile("cp.async.commit_group;" ::: "memory")
#define CP_WAIT2()  asm volatile("cp.async.wait_group 2;" ::: "memory")
#define CP_WAIT1()  asm volatile("cp.async.wait_group 1;" ::: "memory")

__device__ __forceinline__ void ldsm_x4(uint32_t& r0, uint32_t& r1,
                                        uint32_t& r2, uint32_t& r3, uint32_t a) {
    asm volatile("ldmatrix.sync.aligned.m8n8.x4.shared.b16 {%0,%1,%2,%3}, [%4];"
                 : "=r"(r0), "=r"(r1), "=r"(r2), "=r"(r3) : "r"(a));
}
__device__ __forceinline__ void ldsm_x4t(uint32_t& r0, uint32_t& r1,
                                         uint32_t& r2, uint32_t& r3, uint32_t a) {
    asm volatile("ldmatrix.sync.aligned.m8n8.x4.trans.shared.b16 {%0,%1,%2,%3}, [%4];"
                 : "=r"(r0), "=r"(r1), "=r"(r2), "=r"(r3) : "r"(a));
}
__device__ __forceinline__ void mma16816(float* c, const uint32_t* a,
                                         const uint32_t* b) {
    asm volatile("mma.sync.aligned.m16n8k16.row.col.f32.f16.f16.f32 "
                 "{%0,%1,%2,%3}, {%4,%5,%6,%7}, {%8,%9}, {%0,%1,%2,%3};"
                 : "+f"(c[0]), "+f"(c[1]), "+f"(c[2]), "+f"(c[3])
                 : "r"(a[0]), "r"(a[1]), "r"(a[2]), "r"(a[3]),
                   "r"(b[0]), "r"(b[1]));
}
__device__ __forceinline__ uint32_t pack_h2(float a, float b) {
    __half2 h = __floats2half2_rn(a, b);
    return *(uint32_t*)&h;
}

// ---------------------------------------------------------------------------
// Split conversions
// ---------------------------------------------------------------------------
__global__ void split_rows(const float* __restrict__ in, __half* __restrict__ out)
{
    size_t i = (size_t)blockIdx.x * blockDim.x + threadIdx.x;   // over ROWS*CH
    int r = (int)(i >> 10);
    int k = (int)(i & 1023);
    float a = in[i];
    __half hi = __float2half(a);
    __half lo = __float2half(a - __half2float(hi));
    __half* o = out + (size_t)r * K2;
    o[k] = hi; o[CH + k] = lo;
}

__global__ void split_wT(const float* __restrict__ W, __half* __restrict__ Wt, int N)
{
    __shared__ float t[32][33];
    int n0 = blockIdx.x * 32, k0 = blockIdx.y * 32;
    int tx = threadIdx.x, ty = threadIdx.y;   // 32 x 8
    #pragma unroll
    for (int j = 0; j < 32; j += 8)
        t[ty + j][tx] = W[(size_t)(k0 + ty + j) * N + n0 + tx];
    __syncthreads();
    #pragma unroll
    for (int j = 0; j < 32; j += 8) {
        float a = t[tx][ty + j];
        __half hi = __float2half(a);
        __half* o = Wt + (size_t)(n0 + ty + j) * K2 + k0 + tx;
        o[0] = hi; o[CH] = hi;
    }
}

// ---------------------------------------------------------------------------
// mma.sync fp16 GEMM: 128x128 CTA tile, 4 warps (2x2), warp tile 64x64,
// BK=32, 4-stage cp.async ring.
// MODE 0: fp32 out + bias. MODE 1: fp16 hi out (+ lo for cols < CH).
// ---------------------------------------------------------------------------
#define BK   32
#define LDSW 40
#define NCHUNK (K2 / BK)            // 64
#define ASTG (128 * LDSW * 2)       // 10240 B per stage per operand
#define GSM_BYTES (8 * ASTG)        // 81920

template<int MODE>
__global__ __launch_bounds__(128)
void gemm_mma(const __half* __restrict__ A, const __half* __restrict__ Bt,
              const float* __restrict__ bias, float* __restrict__ C,
              __half* __restrict__ Ch, __half* __restrict__ Clo, int N)
{
    extern __shared__ __align__(128) char gsm[];
    const uint32_t sb = smem_u32(gsm);

    const int tid  = threadIdx.x;
    const int lane = tid & 31;
    const int warp = tid >> 5;       // 0..3
    const int wm   = warp >> 1;      // 0..1
    const int wn   = warp & 1;       // 0..1
    const int m0   = blockIdx.y * 128;
    const int n0   = blockIdx.x * 128;

    auto load = [&](int kc, int buf) {
        const uint32_t sA = sb + buf * ASTG;
        const uint32_t sB = sb + 4 * ASTG + buf * ASTG;
        #pragma unroll
        for (int i = 0; i < 4; i++) {
            int c = tid + i * 128;          // 0..511
            int r = c >> 2, j = (c & 3) * 8;
            CP_ASYNC16(sA + (uint32_t)(r * LDSW + j) * 2,
                       A + (size_t)(m0 + r) * K2 + kc * BK + j);
            CP_ASYNC16(sB + (uint32_t)(r * LDSW + j) * 2,
                       Bt + (size_t)(n0 + r) * K2 + kc * BK + j);
        }
    };

    const int lmat = lane >> 3;
    const int lrow = lane & 7;
    const int a_row_base = wm * 64 + ((lmat & 1) << 3) + lrow;
    const int a_k_off    = (lmat >> 1) << 3;
    const int b_row_base = wn * 64 + ((lmat >> 1) << 3) + lrow;
    const int b_k_off    = (lmat & 1) << 3;

    float acc[4][8][4];
    #pragma unroll
    for (int i = 0; i < 4; i++)
        #pragma unroll
        for (int j = 0; j < 8; j++)
            #pragma unroll
            for (int q = 0; q < 4; q++) acc[i][j][q] = 0.0f;

    load(0, 0); CP_COMMIT();
    load(1, 1); CP_COMMIT();
    load(2, 2); CP_COMMIT();

    for (int t = 0; t < NCHUNK; t++) {
        const int buf = t & 3;
        CP_WAIT2();
        __syncthreads();
        if (t + 3 < NCHUNK) load(t + 3, (t + 3) & 3);
        CP_COMMIT();

        const uint32_t sA = sb + buf * ASTG;
        const uint32_t sB = sb + 4 * ASTG + buf * ASTG;
        #pragma unroll
        for (int ks = 0; ks < 2; ks++) {
            uint32_t a[4][4];
            #pragma unroll
            for (int mt = 0; mt < 4; mt++)
                ldsm_x4(a[mt][0], a[mt][1], a[mt][2], a[mt][3],
                        sA + (uint32_t)((a_row_base + mt * 16) * LDSW
                                        + ks * 16 + a_k_off) * 2);
            uint32_t b[4][4];
            #pragma unroll
            for (int nt = 0; nt < 4; nt++)
                ldsm_x4(b[nt][0], b[nt][1], b[nt][2], b[nt][3],
                        sB + (uint32_t)((b_row_base + nt * 16) * LDSW
                                        + ks * 16 + b_k_off) * 2);
            #pragma unroll
            for (int mt = 0; mt < 4; mt++)
                #pragma unroll
                for (int nt = 0; nt < 4; nt++) {
                    mma16816(acc[mt][2 * nt],     a[mt], &b[nt][0]);
                    mma16816(acc[mt][2 * nt + 1], a[mt], &b[nt][2]);
                }
        }
    }

    const int emb = m0 + wm * 64 + (lane >> 2);
    const int enb = n0 + wn * 64 + (lane & 3) * 2;
    #pragma unroll
    for (int mt = 0; mt < 4; mt++) {
        #pragma unroll
        for (int nf = 0; nf < 8; nf++) {
            const int en = enb + nf * 8;
            const int em0 = emb + mt * 16;
            float v0 = acc[mt][nf][0], v1 = acc[mt][nf][1];
            float v2 = acc[mt][nf][2], v3 = acc[mt][nf][3];
            if (MODE == 0) {
                float b0 = bias[en], b1 = bias[en + 1];
                *(float2*)(C + (size_t)em0 * N + en)       = make_float2(v0 + b0, v1 + b1);
                *(float2*)(C + (size_t)(em0 + 8) * N + en) = make_float2(v2 + b0, v3 + b1);
            } else {
                uint32_t hiA = pack_h2(v0, v1);
                uint32_t hiB = pack_h2(v2, v3);
                *(uint32_t*)(Ch + (size_t)em0 * QKV_C + en)       = hiA;
                *(uint32_t*)(Ch + (size_t)(em0 + 8) * QKV_C + en) = hiB;
                if (en < CH) {   // Q third: also write lo residual
                    __half2 hA = *(__half2*)&hiA;
                    __half2 hB = *(__half2*)&hiB;
                    *(uint32_t*)(Clo + (size_t)em0 * CH + en) =
                        pack_h2(v0 - __low2float(hA), v1 - __high2float(hA));
                    *(uint32_t*)(Clo + (size_t)(em0 + 8) * CH + en) =
                        pack_h2(v2 - __low2float(hB), v3 - __high2float(hB));
                }
            }
        }
    }
}

// ---------------------------------------------------------------------------
// Tensorized causal flash attention (fp16 mma, 2-term split).
// Inputs: qkv hi (fp16) + Q lo (fp16), via cp.async; 3-stage KV ring.
// Epilogue writes split-fp16 proj input (g_as).
// ---------------------------------------------------------------------------
#define LDQ 136
#define LDK 72
#define QS_HALVES (128 * LDQ)              // 17408
#define KVSTG_HALVES (2 * 64 * LDK)        // 9216 (K tile then V tile)
#define AT_BYTES ((QS_HALVES + 3 * KVSTG_HALVES) * 2)   // 90112

__global__ __launch_bounds__(256, 2)
void flash_attn_mma(const __half* __restrict__ qh, const __half* __restrict__ qlo,
                    __half* __restrict__ as)
{
    extern __shared__ __align__(128) __half hsm[];
    const uint32_t sQ = smem_u32(hsm);

    const int tid  = threadIdx.x;
    const int lane = tid & 31;
    const int warp = tid >> 5;
    const int bh = blockIdx.y;
    const int b  = bh >> 4;
    const int h  = bh & 15;
    const int m0 = blockIdx.x * 128;

    const __half* Qh = qh + (size_t)b * SEQ * QKV_C + h * HDIM;
    const __half* Ql = qlo + (size_t)b * SEQ * CH + h * HDIM;
    const __half* Kh = Qh + CH;
    const __half* Vh = Qh + 2 * CH;

    auto kv_stage = [&](int s) -> uint32_t {
        return sQ + (uint32_t)(QS_HALVES + s * KVSTG_HALVES) * 2;
    };
    auto load_kv = [&](int t, int s) {
        const uint32_t sK = kv_stage(s);
        const uint32_t sV = sK + (uint32_t)(64 * LDK) * 2;
        #pragma unroll
        for (int i = 0; i < 2; i++) {
            int c = tid + i * 256;            // 0..511
            int r = c >> 3, j = (c & 7) * 8;
            size_t g = (size_t)(t * 64 + r) * QKV_C + j;
            CP_ASYNC16(sK + (uint32_t)(r * LDK + j) * 2, Kh + g);
            CP_ASYNC16(sV + (uint32_t)(r * LDK + j) * 2, Vh + g);
        }
    };

    // prologue: Q (hi|lo) + KV stage 0, then KV stage 1
    #pragma unroll
    for (int i = 0; i < 4; i++) {
        int c = tid + i * 256;                // 0..1023
        int r = c >> 3, j = (c & 7) * 8;
        CP_ASYNC16(sQ + (uint32_t)(r * LDQ + j) * 2,
                   Qh + (size_t)(m0 + r) * QKV_C + j);
        CP_ASYNC16(sQ + (uint32_t)(r * LDQ + 64 + j) * 2,
                   Ql + (size_t)(m0 + r) * CH + j);
    }
    load_kv(0, 0); CP_COMMIT();
    load_kv(1, 1); CP_COMMIT();

    const int lmat = lane >> 3;
    const int lrow = lane & 7;
    const int a_row = warp * 16 + ((lmat & 1) << 3) + lrow;   // A (Qs)
    const int a_k   = (lmat >> 1) << 3;
    const int bs_rb = ((lmat >> 1) << 3) + lrow;              // B for S (K)
    const int bs_k  = (lmat & 1) << 3;
    const int bv_r  = ((lmat & 1) << 3) + lrow;               // B for PV (V, trans)
    const int bv_c  = (lmat >> 1) << 3;

    float m_i[2] = {-1e30f, -1e30f};
    float l_i[2] = {0.0f, 0.0f};
    float oacc[8][4];
    #pragma unroll
    for (int nf = 0; nf < 8; nf++)
        #pragma unroll
        for (int q = 0; q < 4; q++) oacc[nf][q] = 0.0f;

    const int r0 = m0 + warp * 16 + (lane >> 2);
    const int r1 = r0 + 8;

    const int ntiles = (m0 >> 6) + 2;
    for (int t = 0; t < ntiles; t++) {
        const int k0 = t << 6;
        CP_WAIT1();          // stage t (and Q) resident
        __syncthreads();     // all warps done with stage (t-1)%3 compute
        if (t + 2 < ntiles) load_kv(t + 2, (t + 2) % 3);
        CP_COMMIT();

        const uint32_t sK = kv_stage(t % 3);
        const uint32_t sV = sK + (uint32_t)(64 * LDK) * 2;

        // ---- S = (Q_hi + Q_lo) K_hi^T : 8 k16 steps ----
        float sacc[8][4];
        #pragma unroll
        for (int nf = 0; nf < 8; nf++)
            #pragma unroll
            for (int q = 0; q < 4; q++) sacc[nf][q] = 0.0f;

        #pragma unroll
        for (int s = 0; s < 8; s++) {
            const int qb = (s < 4) ? (s & 3) * 16 : 64 + (s & 3) * 16;
            const int kb = (s & 3) * 16;
            uint32_t a[4];
            ldsm_x4(a[0], a[1], a[2], a[3],
                    sQ + (uint32_t)(a_row * LDQ + qb + a_k) * 2);
            #pragma unroll
            for (int nt = 0; nt < 4; nt++) {
                uint32_t bb[4];
                ldsm_x4(bb[0], bb[1], bb[2], bb[3],
                        sK + (uint32_t)((nt * 16 + bs_rb) * LDK + kb + bs_k) * 2);
                mma16816(sacc[nt * 2],     a, &bb[0]);
                mma16816(sacc[nt * 2 + 1], a, &bb[2]);
            }
        }

        // ---- online softmax ----
        const bool need_mask = (k0 + 63 > m0 + warp * 16);
        float mx0 = -1e30f, mx1 = -1e30f;
        #pragma unroll
        for (int nf = 0; nf < 8; nf++) {
            const int cb = k0 + nf * 8 + ((lane & 3) << 1);
            float v0 = sacc[nf][0] * 0.125f;
            float v1 = sacc[nf][1] * 0.125f;
            float v2 = sacc[nf][2] * 0.125f;
            float v3 = sacc[nf][3] * 0.125f;
            if (need_mask) {
                if (cb     > r0) v0 = -1e30f;
                if (cb + 1 > r0) v1 = -1e30f;
                if (cb     > r1) v2 = -1e30f;
                if (cb + 1 > r1) v3 = -1e30f;
            }
            sacc[nf][0] = v0; sacc[nf][1] = v1;
            sacc[nf][2] = v2; sacc[nf][3] = v3;
            mx0 = fmaxf(mx0, fmaxf(v0, v1));
            mx1 = fmaxf(mx1, fmaxf(v2, v3));
        }
        mx0 = fmaxf(mx0, __shfl_xor_sync(0xffffffffu, mx0, 1));
        mx0 = fmaxf(mx0, __shfl_xor_sync(0xffffffffu, mx0, 2));
        mx1 = fmaxf(mx1, __shfl_xor_sync(0xffffffffu, mx1, 1));
        mx1 = fmaxf(mx1, __shfl_xor_sync(0xffffffffu, mx1, 2));

        const float mn0 = fmaxf(m_i[0], mx0);
        const float mn1 = fmaxf(m_i[1], mx1);
        const float cr0 = __expf(m_i[0] - mn0);
        const float cr1 = __expf(m_i[1] - mn1);
        m_i[0] = mn0; m_i[1] = mn1;

        float sm0 = 0.f, sm1 = 0.f;
        #pragma unroll
        for (int nf = 0; nf < 8; nf++) {
            float p0 = __expf(sacc[nf][0] - mn0);
            float p1 = __expf(sacc[nf][1] - mn0);
            float p2 = __expf(sacc[nf][2] - mn1);
            float p3 = __expf(sacc[nf][3] - mn1);
            sacc[nf][0] = p0; sacc[nf][1] = p1;
            sacc[nf][2] = p2; sacc[nf][3] = p3;
            sm0 += p0 + p1;  sm1 += p2 + p3;
        }
        sm0 += __shfl_xor_sync(0xffffffffu, sm0, 1);
        sm0 += __shfl_xor_sync(0xffffffffu, sm0, 2);
        sm1 += __shfl_xor_sync(0xffffffffu, sm1, 1);
        sm1 += __shfl_xor_sync(0xffffffffu, sm1, 2);
        l_i[0] = l_i[0] * cr0 + sm0;
        l_i[1] = l_i[1] * cr1 + sm1;
        #pragma unroll
        for (int nf = 0; nf < 8; nf++) {
            oacc[nf][0] *= cr0; oacc[nf][1] *= cr0;
            oacc[nf][2] *= cr1; oacc[nf][3] *= cr1;
        }

        // ---- O += (P_hi + P_lo) V_hi : 8 k16 steps ----
        #pragma unroll
        for (int s = 0; s < 8; s++) {
            const int ks = s & 3;
            const int kb = ks * 16;
            uint32_t pa[4];
            if (s < 4) {
                pa[0] = pack_h2(sacc[2 * ks][0],     sacc[2 * ks][1]);
                pa[1] = pack_h2(sacc[2 * ks][2],     sacc[2 * ks][3]);
                pa[2] = pack_h2(sacc[2 * ks + 1][0], sacc[2 * ks + 1][1]);
                pa[3] = pack_h2(sacc[2 * ks + 1][2], sacc[2 * ks + 1][3]);
            } else {
                #pragma unroll
                for (int hf = 0; hf < 2; hf++) {
                    const int nf = 2 * ks + hf;
                    uint32_t h01 = pack_h2(sacc[nf][0], sacc[nf][1]);
                    uint32_t h23 = pack_h2(sacc[nf][2], sacc[nf][3]);
                    __half2 b01 = *(__half2*)&h01;
                    __half2 b23 = *(__half2*)&h23;
                    pa[hf * 2]     = pack_h2(sacc[nf][0] - __low2float(b01),
                                             sacc[nf][1] - __high2float(b01));
                    pa[hf * 2 + 1] = pack_h2(sacc[nf][2] - __low2float(b23),
                                             sacc[nf][3] - __high2float(b23));
                }
            }
            #pragma unroll
            for (int nt = 0; nt < 4; nt++) {
                uint32_t bb[4];
                ldsm_x4t(bb[0], bb[1], bb[2], bb[3],
                         sV + (uint32_t)((kb + bv_r) * LDK + nt * 16 + bv_c) * 2);
                mma16816(oacc[nt * 2],     pa, &bb[0]);
                mma16816(oacc[nt * 2 + 1], pa, &bb[2]);
            }
        }
    }

    // ---- epilogue: normalize + fused split write to g_as [hi | lo] ----
    const float inv0 = 1.0f / l_i[0];
    const float inv1 = 1.0f / l_i[1];
    const size_t row0 = (size_t)(b * SEQ + r0) * K2;
    const size_t row1 = (size_t)(b * SEQ + r1) * K2;
    #pragma unroll
    for (int nf = 0; nf < 8; nf++) {
        const int col = h * HDIM + nf * 8 + ((lane & 3) << 1);
        float v0 = oacc[nf][0] * inv0, v1 = oacc[nf][1] * inv0;
        float v2 = oacc[nf][2] * inv1, v3 = oacc[nf][3] * inv1;

        uint32_t hiA = pack_h2(v0, v1);
        __half2 hA = *(__half2*)&hiA;
        uint32_t loA = pack_h2(v0 - __low2float(hA), v1 - __high2float(hA));
        uint32_t hiB = pack_h2(v2, v3);
        __half2 hB = *(__half2*)&hiB;
        uint32_t loB = pack_h2(v2 - __low2float(hB), v3 - __high2float(hB));

        *(uint32_t*)(as + row0 + col)      = hiA;
        *(uint32_t*)(as + row0 + CH + col) = loA;
        *(uint32_t*)(as + row1 + col)      = hiB;
        *(uint32_t*)(as + row1 + CH + col) = loB;
    }
}

// ---------------------------------------------------------------------------
extern "C" void kernel_launch(void* const* d_in, const int* in_sizes, int n_in,
                              void* d_out, int out_size)
{
    const float* x     = (const float*)d_in[0];
    const float* Wqkv  = (const float*)d_in[2];
    const float* Wproj = (const float*)d_in[3];
    const float* bproj = (const float*)d_in[4];
    float* out = (float*)d_out;

    void *p_qh, *p_qlo, *p_xs, *p_as, *p_wqkt, *p_wpt;
    cudaGetSymbolAddress(&p_qh, g_qh);
    cudaGetSymbolAddress(&p_qlo, g_qlo);
    cudaGetSymbolAddress(&p_xs, g_xs);
    cudaGetSymbolAddress(&p_as, g_as);
    cudaGetSymbolAddress(&p_wqkt, g_wqkt);
    cudaGetSymbolAddress(&p_wpt, g_wpt);
    __half* qh   = (__half*)p_qh;
    __half* qlo  = (__half*)p_qlo;
    __half* xs   = (__half*)p_xs;
    __half* as   = (__half*)p_as;
    __half* wqkt = (__half*)p_wqkt;
    __half* wpt  = (__half*)p_wpt;

    cudaFuncSetAttribute(gemm_mma<0>, cudaFuncAttributeMaxDynamicSharedMemorySize,
                         GSM_BYTES);
    cudaFuncSetAttribute(gemm_mma<1>, cudaFuncAttributeMaxDynamicSharedMemorySize,
                         GSM_BYTES);
    cudaFuncSetAttribute(flash_attn_mma, cudaFuncAttributeMaxDynamicSharedMemorySize,
                         AT_BYTES);

    // conversions
    split_rows<<<(ROWS * CH) / 256, 256>>>(x, xs);
    dim3 wt1(QKV_C / 32, CH / 32);
    split_wT<<<wt1, dim3(32, 8)>>>(Wqkv, wqkt, QKV_C);
    dim3 wt2(CH / 32, CH / 32);
    split_wT<<<wt2, dim3(32, 8)>>>(Wproj, wpt, CH);

    // 1) qkv = x @ W_qkv  -> fp16 hi (+ Q lo) directly
    dim3 g1(QKV_C / 128, ROWS / 128);
    gemm_mma<1><<<g1, 128, GSM_BYTES>>>(xs, wqkt, nullptr, nullptr, qh, qlo, QKV_C);

    // 2) causal flash attention -> split proj input (fused)
    dim3 g2(SEQ / 128, BATCH * HEADS);
    flash_attn_mma<<<g2, 256, AT_BYTES>>>(qh, qlo, as);

    // 3) out = attn @ W_proj + b
    dim3 g3(CH / 128, ROWS / 128);
    gemm_mma<0><<<g3, 128, GSM_BYTES>>>(as, wpt, bproj, out, nullptr, nullptr, CH);
}